// round 2
// baseline (speedup 1.0000x reference)
#include <cuda_runtime.h>

// Problem constants (fixed by the dataset)
#define Ee 768
#define Ll 768
#define Hh 12
#define HDd 64
#define Bb 8
#define Nn 1024
#define Mm 1024

// ---------------- scratch (device globals; no allocation allowed) ----------
__device__ float g_xn[Bb * Nn * Ee];                 // LN1(x)
__device__ float g_q [Bb * Nn * Ll];                 // q (B,N,L)
__device__ float g_k [Bb * Mm * Ll];                 // k (B,M,L)
__device__ float g_vt[(long)Bb * Hh * Mm * Ee];      // v transposed (B,H,M,E), bias included
__device__ float g_s [(long)Bb * Nn * Hh * Mm];      // scores (B,N,H,M)
__device__ float g_h [Bb * Nn * Ee];                 // xn + dx
__device__ float g_hn[Bb * Nn * Ee];                 // LN3(h)
__device__ float g_t [Bb * Nn * Ll];                 // relu(hn@w_in+b_in)

// ---------------- block reductions ----------------
__device__ __forceinline__ float blockReduceSum(float val, float* sbuf) {
    int lane = threadIdx.x & 31, wid = threadIdx.x >> 5;
#pragma unroll
    for (int o = 16; o > 0; o >>= 1) val += __shfl_xor_sync(0xffffffffu, val, o);
    if (lane == 0) sbuf[wid] = val;
    __syncthreads();
    if (wid == 0) {
        float r = (lane < (int)(blockDim.x >> 5)) ? sbuf[lane] : 0.f;
#pragma unroll
        for (int o = 16; o > 0; o >>= 1) r += __shfl_xor_sync(0xffffffffu, r, o);
        if (lane == 0) sbuf[32] = r;
    }
    __syncthreads();
    return sbuf[32];
}

__device__ __forceinline__ float blockReduceMax(float val, float* sbuf) {
    int lane = threadIdx.x & 31, wid = threadIdx.x >> 5;
#pragma unroll
    for (int o = 16; o > 0; o >>= 1) val = fmaxf(val, __shfl_xor_sync(0xffffffffu, val, o));
    if (lane == 0) sbuf[wid] = val;
    __syncthreads();
    if (wid == 0) {
        float r = (lane < (int)(blockDim.x >> 5)) ? sbuf[lane] : -3.4e38f;
#pragma unroll
        for (int o = 16; o > 0; o >>= 1) r = fmaxf(r, __shfl_xor_sync(0xffffffffu, r, o));
        if (lane == 0) sbuf[32] = r;
    }
    __syncthreads();
    return sbuf[32];
}

// ---------------- LayerNorm: one block per row of 768 ----------------
__global__ void ln_kernel(const float* __restrict__ x, float* __restrict__ o,
                          const float* __restrict__ g, const float* __restrict__ bt) {
    __shared__ float sbuf[33];
    long row = blockIdx.x;
    const float* p = x + row * Ee;
    int t = threadIdx.x;
    float v0 = p[t], v1 = p[t + 256], v2 = p[t + 512];
    float sum = blockReduceSum(v0 + v1 + v2, sbuf);
    float mean = sum * (1.f / 768.f);
    float d0 = v0 - mean, d1 = v1 - mean, d2 = v2 - mean;
    __syncthreads();
    float sq = blockReduceSum(d0 * d0 + d1 * d1 + d2 * d2, sbuf);
    float rstd = rsqrtf(sq * (1.f / 768.f) + 1e-5f);
    float* q = o + row * Ee;
    q[t]       = d0 * rstd * g[t]       + bt[t];
    q[t + 256] = d1 * rstd * g[t + 256] + bt[t + 256];
    q[t + 512] = d2 * rstd * g[t + 512] + bt[t + 512];
}

// ---------------- generic fp32 SGEMM: C = A@B (+bias)(+relu)(+res), tiles 128x128x8
// mode 0: C = acc (+bias)
// mode 1: C = relu(acc + bias)
// mode 2: C = acc (+bias) + res
// mode 3: v-permute output: row=(b,m), col=(h,e) -> vt[b,h,m,e]; +bias
__global__ void __launch_bounds__(256) sgemm_kernel(
    const float* __restrict__ A, const float* __restrict__ Bm, float* __restrict__ C,
    int Mdim, int Ndim, int Kdim,
    long sA, long sB, long sC, long sR,
    const float* __restrict__ bias, const float* __restrict__ res, int mode)
{
    const int bz = blockIdx.z;
    A  += (long)bz * sA;
    Bm += (long)bz * sB;
    __shared__ float As[8][128];
    __shared__ float Bs[8][128];
    const int tid = threadIdx.x;
    const int arow = tid >> 1, acol = (tid & 1) * 4;
    const int brl = tid >> 5, bcl = (tid & 31) * 4;
    const int tx = tid & 15, ty = tid >> 4;
    const long arow_g = (long)blockIdx.y * 128 + arow;
    const long bcol_g = (long)blockIdx.x * 128 + bcl;
    const float* Aptr = A + arow_g * Kdim + acol;
    const float* Bptr = Bm + bcol_g;
    float acc[8][8] = {};
    for (int k0 = 0; k0 < Kdim; k0 += 8) {
        float4 a4 = *(const float4*)(Aptr + k0);
        float4 b4 = *(const float4*)(Bptr + (long)(k0 + brl) * Ndim);
        As[acol + 0][arow] = a4.x; As[acol + 1][arow] = a4.y;
        As[acol + 2][arow] = a4.z; As[acol + 3][arow] = a4.w;
        *(float4*)&Bs[brl][bcl] = b4;
        __syncthreads();
#pragma unroll
        for (int kk = 0; kk < 8; kk++) {
            float4 a0 = *(const float4*)&As[kk][ty * 8];
            float4 a1 = *(const float4*)&As[kk][ty * 8 + 4];
            float4 b0 = *(const float4*)&Bs[kk][tx * 8];
            float4 b1 = *(const float4*)&Bs[kk][tx * 8 + 4];
            float ar[8] = {a0.x, a0.y, a0.z, a0.w, a1.x, a1.y, a1.z, a1.w};
            float br[8] = {b0.x, b0.y, b0.z, b0.w, b1.x, b1.y, b1.z, b1.w};
#pragma unroll
            for (int i = 0; i < 8; i++)
#pragma unroll
                for (int j = 0; j < 8; j++)
                    acc[i][j] = fmaf(ar[i], br[j], acc[i][j]);
        }
        __syncthreads();
    }
    const long rowbase = (long)blockIdx.y * 128 + ty * 8;
    const int colbase = blockIdx.x * 128 + tx * 8;
#pragma unroll
    for (int i = 0; i < 8; i++) {
        long row = rowbase + i;
#pragma unroll
        for (int j = 0; j < 8; j++) {
            int col = colbase + j;
            float v = acc[i][j];
            if (bias) v += bias[col];
            if (mode == 1) v = fmaxf(v, 0.f);
            if (mode == 2) v += res[(long)bz * sR + row * Ndim + col];
            long cidx;
            if (mode == 3) {
                int bb = (int)(row >> 10), m = (int)(row & 1023);
                int h = col / 768, e = col - h * 768;
                cidx = (((long)(bb * Hh + h) * Mm + m) * Ee) + e;
            } else {
                cidx = (long)bz * sC + row * Ndim + col;
            }
            C[cidx] = v;
        }
    }
}

// ---------------- scores: s[b,n,h,m] = q[b,n,h,:]·k[b,m,h,:], K=64, 64x64 tiles
__global__ void __launch_bounds__(256) scores_kernel(const float* __restrict__ q,
                                                     const float* __restrict__ k,
                                                     float* __restrict__ s)
{
    int bh = blockIdx.z;
    int b = bh / Hh, h = bh - b * Hh;
    int n0 = blockIdx.y * 64, m0 = blockIdx.x * 64;
    const float* qp = q + (long)b * Nn * Ll + h * HDd;
    const float* kp = k + (long)b * Mm * Ll + h * HDd;
    __shared__ float Qs[64][64];  // [d][n]
    __shared__ float Ks[64][64];  // [d][m]
    int tid = threadIdx.x;
#pragma unroll
    for (int i = 0; i < 4; i++) {
        int idx = tid + i * 256;
        int r = idx >> 4, c4 = (idx & 15) * 4;
        float4 qv = *(const float4*)(qp + (long)(n0 + r) * Ll + c4);
        Qs[c4 + 0][r] = qv.x; Qs[c4 + 1][r] = qv.y;
        Qs[c4 + 2][r] = qv.z; Qs[c4 + 3][r] = qv.w;
        float4 kv = *(const float4*)(kp + (long)(m0 + r) * Ll + c4);
        Ks[c4 + 0][r] = kv.x; Ks[c4 + 1][r] = kv.y;
        Ks[c4 + 2][r] = kv.z; Ks[c4 + 3][r] = kv.w;
    }
    __syncthreads();
    int tx = tid & 15, ty = tid >> 4;
    float acc[4][4] = {};
#pragma unroll
    for (int d = 0; d < 64; d++) {
        float4 a = *(const float4*)&Qs[d][ty * 4];
        float4 bb4 = *(const float4*)&Ks[d][tx * 4];
        float ar[4] = {a.x, a.y, a.z, a.w};
        float br[4] = {bb4.x, bb4.y, bb4.z, bb4.w};
#pragma unroll
        for (int i = 0; i < 4; i++)
#pragma unroll
            for (int j = 0; j < 4; j++)
                acc[i][j] = fmaf(ar[i], br[j], acc[i][j]);
    }
#pragma unroll
    for (int i = 0; i < 4; i++) {
        int n = n0 + ty * 4 + i;
        long base = (((long)b * Nn + n) * Hh + h) * Mm + m0 + tx * 4;
        float4 o = make_float4(acc[i][0], acc[i][1], acc[i][2], acc[i][3]);
        *(float4*)&s[base] = o;
    }
}

// ---------------- softmax over last dim (1024), scale 1/8, in place ----------
__global__ void softmax_kernel(float* __restrict__ s) {
    __shared__ float sbuf[33];
    long row = blockIdx.x;
    float* p = s + row * 1024;
    int t = threadIdx.x;
    float4 v = ((float4*)p)[t];
    const float sc = 0.125f;  // 1/sqrt(64)
    v.x *= sc; v.y *= sc; v.z *= sc; v.w *= sc;
    float mx = blockReduceMax(fmaxf(fmaxf(v.x, v.y), fmaxf(v.z, v.w)), sbuf);
    float e0 = __expf(v.x - mx), e1 = __expf(v.y - mx);
    float e2 = __expf(v.z - mx), e3 = __expf(v.w - mx);
    __syncthreads();
    float sum = blockReduceSum(e0 + e1 + e2 + e3, sbuf);
    float inv = 1.f / sum;
    ((float4*)p)[t] = make_float4(e0 * inv, e1 * inv, e2 * inv, e3 * inv);
}

// ---------------- launch ----------------
extern "C" void kernel_launch(void* const* d_in, const int* in_sizes, int n_in,
                              void* d_out, int out_size) {
    const float* x     = (const float*)d_in[0];
    const float* y     = (const float*)d_in[1];
    const float* ln1_g = (const float*)d_in[2];
    const float* ln1_b = (const float*)d_in[3];
    const float* ln2_g = (const float*)d_in[4];
    const float* ln2_b = (const float*)d_in[5];
    const float* ln3_g = (const float*)d_in[6];
    const float* ln3_b = (const float*)d_in[7];
    const float* wq    = (const float*)d_in[8];
    const float* bq    = (const float*)d_in[9];
    const float* wk    = (const float*)d_in[10];
    const float* bk    = (const float*)d_in[11];
    const float* wv    = (const float*)d_in[12];
    const float* bv    = (const float*)d_in[13];
    const float* w_in  = (const float*)d_in[14];
    const float* b_in  = (const float*)d_in[15];
    const float* w_out = (const float*)d_in[16];
    const float* b_out = (const float*)d_in[17];

    float* out1 = (float*)d_out;                      // h + mlp  (B,N,E)
    float* yn   = out1 + (long)Bb * Nn * Ee;          // yn       (B,M,E)

    float *xn, *qb, *kb, *vt, *sb, *hb, *hnb, *tb;
    cudaGetSymbolAddress((void**)&xn,   g_xn);
    cudaGetSymbolAddress((void**)&qb,   g_q);
    cudaGetSymbolAddress((void**)&kb,   g_k);
    cudaGetSymbolAddress((void**)&vt,   g_vt);
    cudaGetSymbolAddress((void**)&sb,   g_s);
    cudaGetSymbolAddress((void**)&hb,   g_h);
    cudaGetSymbolAddress((void**)&hnb,  g_hn);
    cudaGetSymbolAddress((void**)&tb,   g_t);

    // 1) LayerNorms of inputs (yn goes straight to output buffer)
    ln_kernel<<<Bb * Nn, 256>>>(x, xn, ln1_g, ln1_b);
    ln_kernel<<<Bb * Mm, 256>>>(y, yn, ln2_g, ln2_b);

    // 2) q, k projections: (8192x768) @ (768x768) + bias
    {
        dim3 g(Ll / 128, (Bb * Nn) / 128, 1);
        sgemm_kernel<<<g, 256>>>(xn, wq, qb, Bb * Nn, Ll, Ee, 0, 0, 0, 0, bq, nullptr, 0);
        sgemm_kernel<<<g, 256>>>(yn, wk, kb, Bb * Mm, Ll, Ee, 0, 0, 0, 0, bk, nullptr, 0);
    }

    // 3) v projection with permuted output -> vt (B,H,M,E), bias INCLUDED here
    {
        dim3 g((Ee * Hh) / 128, (Bb * Mm) / 128, 1);
        sgemm_kernel<<<g, 256>>>(yn, wv, vt, Bb * Mm, Ee * Hh, Ee, 0, 0, 0, 0, bv, nullptr, 3);
    }

    // 4) attention scores s[b,n,h,m] = q·k (K=64)
    {
        dim3 g(Mm / 64, Nn / 64, Bb * Hh);
        scores_kernel<<<g, 256>>>(qb, kb, sb);
    }

    // 5) softmax over m (scale 1/8 folded in)
    softmax_kernel<<<Bb * Nn * Hh, 256>>>(sb);

    // 6) dx GEMM (batched over b): h = s[b](1024x12288) @ vt[b](12288x768) + xn
    //    NOTE: bias=nullptr — bv already lives inside vt; softmax rows sum to 1
    //    so its contribution comes through the GEMM (previously double-counted).
    {
        dim3 g(Ee / 128, Nn / 128, Bb);
        sgemm_kernel<<<g, 256>>>(sb, vt, hb, Nn, Ee, Hh * Mm,
                                 (long)Nn * Hh * Mm, (long)Hh * Mm * Ee,
                                 (long)Nn * Ee, (long)Nn * Ee, nullptr, xn, 2);
    }

    // 7) LN3
    ln_kernel<<<Bb * Nn, 256>>>(hb, hnb, ln3_g, ln3_b);

    // 8) MLP: t = relu(hn @ w_in + b_in); out1 = hn + t @ w_out + b_out
    {
        dim3 g(Ll / 128, (Bb * Nn) / 128, 1);
        sgemm_kernel<<<g, 256>>>(hnb, w_in, tb, Bb * Nn, Ll, Ee, 0, 0, 0, 0, b_in, nullptr, 1);
        sgemm_kernel<<<g, 256>>>(tb, w_out, out1, Bb * Nn, Ee, Ll, 0, 0, 0, 0, b_out, hnb, 2);
    }
}

// round 6
// speedup vs baseline: 1.4783x; 1.4783x over previous
#include <cuda_runtime.h>
#include <cuda_bf16.h>
#include <cstdint>

// Problem constants
#define Ee 768
#define Ll 768
#define Hh 12
#define HDd 64
#define Bb 8
#define Nn 1024
#define Mm 1024
#define KV 12288           // H*M : K of the dx GEMM
#define KV3 36864          // 3*KV (augmented)
#define KE3 2304           // 3*E  (augmented)

// ---------------- scratch (device globals) ----------------
__device__ float g_xn[Bb * Nn * Ee];
__device__ float g_q [Bb * Nn * Ll];
__device__ float g_k [Bb * Mm * Ll];
__device__ float g_s [(long)Bb * Nn * Hh * Mm];                  // fp32 scores
__device__ __nv_bfloat16 g_sa [(long)Bb * Nn * KV3];             // aug softmax probs [(b,n)][K'=36864]
__device__ __nv_bfloat16 g_vtb[(long)Bb * Ee * KV3];             // aug v  [(b,e)][K'] (B operand of dx)
__device__ __nv_bfloat16 g_ya [(long)Bb * Mm * KE3];             // aug yn [(b,m)][K'=2304]
__device__ __nv_bfloat16 g_wb [(long)(Ee * Hh) * KE3];           // aug wv [n=9216][K'=2304]
__device__ float g_h [Bb * Nn * Ee];
__device__ float g_hn[Bb * Nn * Ee];
__device__ float g_t [Bb * Nn * Ll];

// ================= helpers =================
__device__ __forceinline__ uint32_t smem_u32(const void* p) {
    uint32_t a;
    asm("{ .reg .u64 t; cvta.to.shared.u64 t, %1; cvt.u32.u64 %0, t; }" : "=r"(a) : "l"(p));
    return a;
}

#define CP_ASYNC16(dst, src) \
    asm volatile("cp.async.cg.shared.global [%0], [%1], 16;" :: "r"(dst), "l"(src))
#define CP_COMMIT() asm volatile("cp.async.commit_group;" ::: "memory")
#define CP_WAIT1()  asm volatile("cp.async.wait_group 1;" ::: "memory")
#define CP_WAIT0()  asm volatile("cp.async.wait_group 0;" ::: "memory")

#define LDSM4(r0, r1, r2, r3, addr) \
    asm volatile("ldmatrix.sync.aligned.m8n8.x4.shared.b16 {%0,%1,%2,%3}, [%4];" \
        : "=r"(r0), "=r"(r1), "=r"(r2), "=r"(r3) : "r"(addr))

#define MMA_BF16(d, a, b) \
    asm volatile("mma.sync.aligned.m16n8k16.row.col.f32.bf16.bf16.f32 " \
        "{%0,%1,%2,%3}, {%4,%5,%6,%7}, {%8,%9}, {%0,%1,%2,%3};" \
        : "+f"((d)[0]), "+f"((d)[1]), "+f"((d)[2]), "+f"((d)[3]) \
        : "r"((a)[0]), "r"((a)[1]), "r"((a)[2]), "r"((a)[3]), "r"((b)[0]), "r"((b)[1]))

// ================= reductions =================
__device__ __forceinline__ float blockReduceSum(float val, float* sbuf) {
    int lane = threadIdx.x & 31, wid = threadIdx.x >> 5;
#pragma unroll
    for (int o = 16; o > 0; o >>= 1) val += __shfl_xor_sync(0xffffffffu, val, o);
    if (lane == 0) sbuf[wid] = val;
    __syncthreads();
    if (wid == 0) {
        float r = (lane < (int)(blockDim.x >> 5)) ? sbuf[lane] : 0.f;
#pragma unroll
        for (int o = 16; o > 0; o >>= 1) r += __shfl_xor_sync(0xffffffffu, r, o);
        if (lane == 0) sbuf[32] = r;
    }
    __syncthreads();
    return sbuf[32];
}
__device__ __forceinline__ float blockReduceMax(float val, float* sbuf) {
    int lane = threadIdx.x & 31, wid = threadIdx.x >> 5;
#pragma unroll
    for (int o = 16; o > 0; o >>= 1) val = fmaxf(val, __shfl_xor_sync(0xffffffffu, val, o));
    if (lane == 0) sbuf[wid] = val;
    __syncthreads();
    if (wid == 0) {
        float r = (lane < (int)(blockDim.x >> 5)) ? sbuf[lane] : -3.4e38f;
#pragma unroll
        for (int o = 16; o > 0; o >>= 1) r = fmaxf(r, __shfl_xor_sync(0xffffffffu, r, o));
        if (lane == 0) sbuf[32] = r;
    }
    __syncthreads();
    return sbuf[32];
}

// ================= LayerNorm =================
__global__ void ln_kernel(const float* __restrict__ x, float* __restrict__ o,
                          const float* __restrict__ g, const float* __restrict__ bt) {
    __shared__ float sbuf[33];
    long row = blockIdx.x;
    const float* p = x + row * Ee;
    int t = threadIdx.x;
    float v0 = p[t], v1 = p[t + 256], v2 = p[t + 512];
    float sum = blockReduceSum(v0 + v1 + v2, sbuf);
    float mean = sum * (1.f / 768.f);
    float d0 = v0 - mean, d1 = v1 - mean, d2 = v2 - mean;
    __syncthreads();
    float sq = blockReduceSum(d0 * d0 + d1 * d1 + d2 * d2, sbuf);
    float rstd = rsqrtf(sq * (1.f / 768.f) + 1e-5f);
    float* q = o + row * Ee;
    q[t]       = d0 * rstd * g[t]       + bt[t];
    q[t + 256] = d1 * rstd * g[t + 256] + bt[t + 256];
    q[t + 512] = d2 * rstd * g[t + 512] + bt[t + 512];
}

// ================= fp32 SGEMM (q, k, MLP) =================
__global__ void __launch_bounds__(256) sgemm_kernel(
    const float* __restrict__ A, const float* __restrict__ Bm, float* __restrict__ C,
    int Ndim, int Kdim, const float* __restrict__ bias, const float* __restrict__ res, int mode)
{
    __shared__ float As[8][128];
    __shared__ float Bs[8][128];
    const int tid = threadIdx.x;
    const int arow = tid >> 1, acol = (tid & 1) * 4;
    const int brl = tid >> 5, bcl = (tid & 31) * 4;
    const int tx = tid & 15, ty = tid >> 4;
    const long arow_g = (long)blockIdx.y * 128 + arow;
    const long bcol_g = (long)blockIdx.x * 128 + bcl;
    const float* Aptr = A + arow_g * Kdim + acol;
    const float* Bptr = Bm + bcol_g;
    float acc[8][8] = {};
    for (int k0 = 0; k0 < Kdim; k0 += 8) {
        float4 a4 = *(const float4*)(Aptr + k0);
        float4 b4 = *(const float4*)(Bptr + (long)(k0 + brl) * Ndim);
        As[acol + 0][arow] = a4.x; As[acol + 1][arow] = a4.y;
        As[acol + 2][arow] = a4.z; As[acol + 3][arow] = a4.w;
        *(float4*)&Bs[brl][bcl] = b4;
        __syncthreads();
#pragma unroll
        for (int kk = 0; kk < 8; kk++) {
            float4 a0 = *(const float4*)&As[kk][ty * 8];
            float4 a1 = *(const float4*)&As[kk][ty * 8 + 4];
            float4 b0 = *(const float4*)&Bs[kk][tx * 8];
            float4 b1 = *(const float4*)&Bs[kk][tx * 8 + 4];
            float ar[8] = {a0.x, a0.y, a0.z, a0.w, a1.x, a1.y, a1.z, a1.w};
            float br[8] = {b0.x, b0.y, b0.z, b0.w, b1.x, b1.y, b1.z, b1.w};
#pragma unroll
            for (int i = 0; i < 8; i++)
#pragma unroll
                for (int j = 0; j < 8; j++)
                    acc[i][j] = fmaf(ar[i], br[j], acc[i][j]);
        }
        __syncthreads();
    }
    const long rowbase = (long)blockIdx.y * 128 + ty * 8;
    const int colbase = blockIdx.x * 128 + tx * 8;
#pragma unroll
    for (int i = 0; i < 8; i++) {
        long row = rowbase + i;
#pragma unroll
        for (int j = 0; j < 8; j++) {
            int col = colbase + j;
            float v = acc[i][j];
            if (bias) v += bias[col];
            if (mode == 1) v = fmaxf(v, 0.f);
            if (mode == 2) v += res[row * Ndim + col];
            C[row * Ndim + col] = v;
        }
    }
}

// ================= scores (K=64, per-head) =================
__global__ void __launch_bounds__(256) scores_kernel(const float* __restrict__ q,
                                                     const float* __restrict__ k,
                                                     float* __restrict__ s)
{
    int bh = blockIdx.z;
    int b = bh / Hh, h = bh - b * Hh;
    int n0 = blockIdx.y * 64, m0 = blockIdx.x * 64;
    const float* qp = q + (long)b * Nn * Ll + h * HDd;
    const float* kp = k + (long)b * Mm * Ll + h * HDd;
    __shared__ float Qs[64][64];
    __shared__ float Ks[64][64];
    int tid = threadIdx.x;
#pragma unroll
    for (int i = 0; i < 4; i++) {
        int idx = tid + i * 256;
        int r = idx >> 4, c4 = (idx & 15) * 4;
        float4 qv = *(const float4*)(qp + (long)(n0 + r) * Ll + c4);
        Qs[c4 + 0][r] = qv.x; Qs[c4 + 1][r] = qv.y;
        Qs[c4 + 2][r] = qv.z; Qs[c4 + 3][r] = qv.w;
        float4 kv = *(const float4*)(kp + (long)(m0 + r) * Ll + c4);
        Ks[c4 + 0][r] = kv.x; Ks[c4 + 1][r] = kv.y;
        Ks[c4 + 2][r] = kv.z; Ks[c4 + 3][r] = kv.w;
    }
    __syncthreads();
    int tx = tid & 15, ty = tid >> 4;
    float acc[4][4] = {};
#pragma unroll
    for (int d = 0; d < 64; d++) {
        float4 a = *(const float4*)&Qs[d][ty * 4];
        float4 bb4 = *(const float4*)&Ks[d][tx * 4];
        float ar[4] = {a.x, a.y, a.z, a.w};
        float br[4] = {bb4.x, bb4.y, bb4.z, bb4.w};
#pragma unroll
        for (int i = 0; i < 4; i++)
#pragma unroll
            for (int j = 0; j < 4; j++)
                acc[i][j] = fmaf(ar[i], br[j], acc[i][j]);
    }
#pragma unroll
    for (int i = 0; i < 4; i++) {
        int n = n0 + ty * 4 + i;
        long base = (((long)b * Nn + n) * Hh + h) * Mm + m0 + tx * 4;
        *(float4*)&s[base] = make_float4(acc[i][0], acc[i][1], acc[i][2], acc[i][3]);
    }
}

// ========== softmax: fp32 in -> augmented bf16 out ([Ph|Ph|Pl] over K'=36864) ==========
__global__ void softmax_aug_kernel(const float* __restrict__ s, __nv_bfloat16* __restrict__ sa) {
    __shared__ float sbuf[33];
    long srow = blockIdx.x;                 // = (b*N + n)*H + h
    const float* p = s + srow * 1024;
    int h  = (int)(srow % Hh);
    long bn = srow / Hh;
    __nv_bfloat16* dst = sa + bn * KV3 + h * 1024;
    int t = threadIdx.x;
    float4 v = ((const float4*)p)[t];
    const float sc = 0.125f;
    v.x *= sc; v.y *= sc; v.z *= sc; v.w *= sc;
    float mx = blockReduceMax(fmaxf(fmaxf(v.x, v.y), fmaxf(v.z, v.w)), sbuf);
    float e0 = __expf(v.x - mx), e1 = __expf(v.y - mx);
    float e2 = __expf(v.z - mx), e3 = __expf(v.w - mx);
    __syncthreads();
    float sum = blockReduceSum(e0 + e1 + e2 + e3, sbuf);
    float inv = 1.f / sum;
    float pv[4] = {e0 * inv, e1 * inv, e2 * inv, e3 * inv};
    __nv_bfloat16 hi[4], lo[4];
#pragma unroll
    for (int i = 0; i < 4; i++) {
        hi[i] = __float2bfloat16(pv[i]);
        lo[i] = __float2bfloat16(pv[i] - __bfloat162float(hi[i]));
    }
    int m = t * 4;
    __nv_bfloat162 h01 = __nv_bfloat162(hi[0], hi[1]);
    __nv_bfloat162 h23 = __nv_bfloat162(hi[2], hi[3]);
    __nv_bfloat162 l01 = __nv_bfloat162(lo[0], lo[1]);
    __nv_bfloat162 l23 = __nv_bfloat162(lo[2], lo[3]);
    *(__nv_bfloat162*)(dst + m)          = h01;  *(__nv_bfloat162*)(dst + m + 2)          = h23;
    *(__nv_bfloat162*)(dst + KV + m)     = h01;  *(__nv_bfloat162*)(dst + KV + m + 2)     = h23;
    *(__nv_bfloat162*)(dst + 2 * KV + m) = l01;  *(__nv_bfloat162*)(dst + 2 * KV + m + 2) = l23;
}

// ========== conv: yn fp32 (rows x 768) -> aug bf16 (rows x 2304) [Ah|Ah|Al] ==========
__global__ void conv_rowsplit_kernel(const float* __restrict__ in, __nv_bfloat16* __restrict__ out) {
    long row = blockIdx.x;
    int t = threadIdx.x;                    // 192 threads, 4 elems each
    float4 v = ((const float4*)(in + row * Ee))[t];
    float pv[4] = {v.x, v.y, v.z, v.w};
    __nv_bfloat16 hi[4], lo[4];
#pragma unroll
    for (int i = 0; i < 4; i++) {
        hi[i] = __float2bfloat16(pv[i]);
        lo[i] = __float2bfloat16(pv[i] - __bfloat162float(hi[i]));
    }
    __nv_bfloat16* dst = out + row * KE3;
    int k = t * 4;
    __nv_bfloat162 h01 = __nv_bfloat162(hi[0], hi[1]);
    __nv_bfloat162 h23 = __nv_bfloat162(hi[2], hi[3]);
    __nv_bfloat162 l01 = __nv_bfloat162(lo[0], lo[1]);
    __nv_bfloat162 l23 = __nv_bfloat162(lo[2], lo[3]);
    *(__nv_bfloat162*)(dst + k)          = h01;  *(__nv_bfloat162*)(dst + k + 2)          = h23;
    *(__nv_bfloat162*)(dst + Ee + k)     = h01;  *(__nv_bfloat162*)(dst + Ee + k + 2)     = h23;
    *(__nv_bfloat162*)(dst + 2 * Ee + k) = l01;  *(__nv_bfloat162*)(dst + 2 * Ee + k + 2) = l23;
}

// ========== conv: wv fp32 (768 x 9216) -> aug bf16 (9216 x 2304) [Bh;Bl;Bh], transposed ==========
__global__ void conv_wv_kernel(const float* __restrict__ wv, __nv_bfloat16* __restrict__ wb) {
    __shared__ float tile[32][33];
    int k0 = blockIdx.x * 32, n0 = blockIdx.y * 32;
    int tx = threadIdx.x, ty = threadIdx.y;
    tile[ty][tx] = wv[(long)(k0 + ty) * (Ee * Hh) + n0 + tx];
    __syncthreads();
    int n = n0 + ty, k = k0 + tx;
    float v = tile[tx][ty];
    __nv_bfloat16 hi = __float2bfloat16(v);
    __nv_bfloat16 lo = __float2bfloat16(v - __bfloat162float(hi));
    __nv_bfloat16* dst = wb + (long)n * KE3;
    dst[k] = hi; dst[Ee + k] = lo; dst[2 * Ee + k] = hi;
}

// ================= bf16 tensor-core GEMM via mma.sync =================
// C[M,N] = A[M,K'] @ B[N,K']^T ; tile 128x128, K-chunk 32, 8 warps (4m x 2n)
// mode 0: v-proj: D + bias -> bf16 split -> scattered aug writes to Cvt
// mode 1: dx:     D + res  -> fp32 Cf
__global__ void __launch_bounds__(256) gemm_mma_kernel(
    const __nv_bfloat16* __restrict__ A, const __nv_bfloat16* __restrict__ Bm,
    int Kp, long sAb, long sBb,
    const float* __restrict__ bias,
    const float* __restrict__ res, long sRes, float* __restrict__ Cf, long sC, int ldc,
    __nv_bfloat16* __restrict__ Cvt, int mode)
{
    __shared__ alignas(128) __nv_bfloat16 smA[2][128 * 32];
    __shared__ alignas(128) __nv_bfloat16 smB[2][128 * 32];
    const int tid = threadIdx.x, wid = tid >> 5, lane = tid & 31;
    const int bz = blockIdx.z;
    const int n0 = blockIdx.x * 128, m0 = blockIdx.y * 128;
    const __nv_bfloat16* Ap = A + (long)bz * sAb;
    const __nv_bfloat16* Bp = Bm + (long)bz * sBb;

    // ---- staging setup: thread t<128 loads A row t; t>=128 loads B row t-128.
    const int isA = (tid < 128);
    const int srow = isA ? tid : tid - 128;
    const __nv_bfloat16* gsrc = isA ? (Ap + (long)(m0 + srow) * Kp)
                                    : (Bp + (long)(n0 + srow) * Kp);
    uint32_t sdst0 = smem_u32(isA ? (const void*)&smA[0][0] : (const void*)&smB[0][0]) + srow * 64;
    uint32_t dsw[4];
#pragma unroll
    for (int s2 = 0; s2 < 4; s2++) dsw[s2] = (uint32_t)((s2 ^ ((srow >> 1) & 3)) << 4);

    const int nchunks = Kp >> 5;

    // prefetch chunk 0 -> buf 0
    {
#pragma unroll
        for (int s2 = 0; s2 < 4; s2++) CP_ASYNC16(sdst0 + dsw[s2], gsrc + s2 * 8);
        CP_COMMIT();
    }

    // ---- warp compute indexing
    const int wm = wid & 3, wn = wid >> 2;
    const int lrow = lane & 7;
    int rowA[2], rowB[4];
#pragma unroll
    for (int mt = 0; mt < 2; mt++) rowA[mt] = wm * 32 + mt * 16 + ((lane >> 3) & 1) * 8 + lrow;
#pragma unroll
    for (int np = 0; np < 4; np++) rowB[np] = wn * 64 + np * 16 + (lane >> 4) * 8 + lrow;
    const int segAq = (lane >> 4);
    const int segBq = ((lane >> 3) & 1);
    const uint32_t smA0 = smem_u32(&smA[0][0]);
    const uint32_t smB0 = smem_u32(&smB[0][0]);

    float acc[2][8][4] = {};

    for (int c = 0; c < nchunks; c++) {
        const int buf = c & 1;
        if (c + 1 < nchunks) {
            const __nv_bfloat16* p = gsrc + (long)(c + 1) * 32;
            uint32_t d = sdst0 + (uint32_t)(((c + 1) & 1) * (128 * 32 * 2));
#pragma unroll
            for (int s2 = 0; s2 < 4; s2++) CP_ASYNC16(d + dsw[s2], p + s2 * 8);
            CP_COMMIT();
            CP_WAIT1();
        } else {
            CP_WAIT0();
        }
        __syncthreads();
        const uint32_t aB = smA0 + (uint32_t)(buf * (128 * 32 * 2));
        const uint32_t bB = smB0 + (uint32_t)(buf * (128 * 32 * 2));
#pragma unroll
        for (int ks = 0; ks < 2; ks++) {
            uint32_t aF[2][4];
            uint32_t bF[8][2];
#pragma unroll
            for (int mt = 0; mt < 2; mt++) {
                int row = rowA[mt], seg = ks * 2 + segAq;
                uint32_t ad = aB + row * 64 + (uint32_t)((seg ^ ((row >> 1) & 3)) << 4);
                LDSM4(aF[mt][0], aF[mt][1], aF[mt][2], aF[mt][3], ad);
            }
#pragma unroll
            for (int np = 0; np < 4; np++) {
                int row = rowB[np], seg = ks * 2 + segBq;
                uint32_t bd = bB + row * 64 + (uint32_t)((seg ^ ((row >> 1) & 3)) << 4);
                LDSM4(bF[2 * np][0], bF[2 * np][1], bF[2 * np + 1][0], bF[2 * np + 1][1], bd);
            }
#pragma unroll
            for (int mt = 0; mt < 2; mt++)
#pragma unroll
                for (int nt = 0; nt < 8; nt++)
                    MMA_BF16(acc[mt][nt], aF[mt], bF[nt]);
        }
        __syncthreads();
    }

    // ---- epilogue
    const int r_in = lane >> 2;            // 0..7
    const int c_in = (lane & 3) * 2;       // 0,2,4,6
#pragma unroll
    for (int mt = 0; mt < 2; mt++) {
#pragma unroll
        for (int nt = 0; nt < 8; nt++) {
            int col0 = n0 + wn * 64 + nt * 8 + c_in;
#pragma unroll
            for (int half = 0; half < 2; half++) {
                int row = m0 + wm * 32 + mt * 16 + r_in + half * 8;
                float v0 = acc[mt][nt][half * 2 + 0];
                float v1 = acc[mt][nt][half * 2 + 1];
                if (mode == 1) {
                    const float* rs = res + (long)bz * sRes + (long)row * ldc + col0;
                    float2 rv = *(const float2*)rs;
                    float2 o = make_float2(v0 + rv.x, v1 + rv.y);
                    *(float2*)(Cf + (long)bz * sC + (long)row * ldc + col0) = o;
                } else {
                    int b = row >> 10, m = row & 1023;
#pragma unroll
                    for (int j = 0; j < 2; j++) {
                        int col = col0 + j;
                        float v = (j ? v1 : v0) + bias[col];
                        int h = col / Ee, e = col - h * Ee;
                        __nv_bfloat16 hi = __float2bfloat16(v);
                        __nv_bfloat16 lo = __float2bfloat16(v - __bfloat162float(hi));
                        long bk = ((long)(b * Ee + e)) * KV3 + h * 1024 + m;
                        Cvt[bk] = hi; Cvt[bk + KV] = lo; Cvt[bk + 2 * KV] = hi;
                    }
                }
            }
        }
    }
}

// ================= launch =================
extern "C" void kernel_launch(void* const* d_in, const int* in_sizes, int n_in,
                              void* d_out, int out_size) {
    const float* x     = (const float*)d_in[0];
    const float* y     = (const float*)d_in[1];
    const float* ln1_g = (const float*)d_in[2];
    const float* ln1_b = (const float*)d_in[3];
    const float* ln2_g = (const float*)d_in[4];
    const float* ln2_b = (const float*)d_in[5];
    const float* ln3_g = (const float*)d_in[6];
    const float* ln3_b = (const float*)d_in[7];
    const float* wq    = (const float*)d_in[8];
    const float* bq    = (const float*)d_in[9];
    const float* wk    = (const float*)d_in[10];
    const float* bk    = (const float*)d_in[11];
    const float* wv    = (const float*)d_in[12];
    const float* bv    = (const float*)d_in[13];
    const float* w_in  = (const float*)d_in[14];
    const float* b_in  = (const float*)d_in[15];
    const float* w_out = (const float*)d_in[16];
    const float* b_out = (const float*)d_in[17];

    float* out1 = (float*)d_out;
    float* yn   = out1 + (long)Bb * Nn * Ee;

    float *xn, *qb, *kb, *sb, *hb, *hnb, *tb;
    __nv_bfloat16 *sa, *vtb, *ya, *wb;
    cudaGetSymbolAddress((void**)&xn,  g_xn);
    cudaGetSymbolAddress((void**)&qb,  g_q);
    cudaGetSymbolAddress((void**)&kb,  g_k);
    cudaGetSymbolAddress((void**)&sb,  g_s);
    cudaGetSymbolAddress((void**)&hb,  g_h);
    cudaGetSymbolAddress((void**)&hnb, g_hn);
    cudaGetSymbolAddress((void**)&tb,  g_t);
    cudaGetSymbolAddress((void**)&sa,  g_sa);
    cudaGetSymbolAddress((void**)&vtb, g_vtb);
    cudaGetSymbolAddress((void**)&ya,  g_ya);
    cudaGetSymbolAddress((void**)&wb,  g_wb);

    // 1) LayerNorms
    ln_kernel<<<Bb * Nn, 256>>>(x, xn, ln1_g, ln1_b);
    ln_kernel<<<Bb * Mm, 256>>>(y, yn, ln2_g, ln2_b);

    // 2) conversions for the v-proj tensor GEMM
    conv_rowsplit_kernel<<<Bb * Mm, 192>>>(yn, ya);
    {
        dim3 blk(32, 32), g(Ee / 32, (Ee * Hh) / 32);
        conv_wv_kernel<<<g, blk>>>(wv, wb);
    }

    // 3) q, k projections (fp32)
    {
        dim3 g(Ll / 128, (Bb * Nn) / 128);
        sgemm_kernel<<<g, 256>>>(xn, wq, qb, Ll, Ee, bq, nullptr, 0);
        sgemm_kernel<<<g, 256>>>(yn, wk, kb, Ll, Ee, bk, nullptr, 0);
    }

    // 4) v projection on tensor cores -> vtB (augmented bf16, [b,e][K'])
    {
        dim3 g((Ee * Hh) / 128, (Bb * Mm) / 128, 1);
        gemm_mma_kernel<<<g, 256>>>(ya, wb, KE3, 0, 0, bv,
                                    nullptr, 0, nullptr, 0, 0, vtb, 0);
    }

    // 5) scores (fp32)
    {
        dim3 g(Mm / 64, Nn / 64, Bb * Hh);
        scores_kernel<<<g, 256>>>(qb, kb, sb);
    }

    // 6) softmax -> augmented bf16 probs
    softmax_aug_kernel<<<Bb * Nn * Hh, 256>>>(sb, sa);

    // 7) dx on tensor cores: h = s @ vt + xn
    {
        dim3 g(Ee / 128, Nn / 128, Bb);
        gemm_mma_kernel<<<g, 256>>>(sa, vtb, KV3,
                                    (long)Nn * KV3, (long)Ee * KV3, nullptr,
                                    xn, (long)Nn * Ee, hb, (long)Nn * Ee, Ee,
                                    nullptr, 1);
    }

    // 8) LN3 + MLP (fp32)
    ln_kernel<<<Bb * Nn, 256>>>(hb, hnb, ln3_g, ln3_b);
    {
        dim3 g(Ll / 128, (Bb * Nn) / 128);
        sgemm_kernel<<<g, 256>>>(hnb, w_in, tb, Ll, Ee, b_in, nullptr, 1);
        sgemm_kernel<<<g, 256>>>(tb, w_out, out1, Ee, Ll, b_out, hnb, 2);
    }
}

// round 7
// speedup vs baseline: 2.4901x; 1.6844x over previous
#include <cuda_runtime.h>
#include <cuda_bf16.h>
#include <cstdint>

// Problem constants
#define Ee 768
#define Ll 768
#define Hh 12
#define HDd 64
#define Bb 8
#define Nn 1024
#define Mm 1024
#define KV 12288           // H*M : K of the dx GEMM

// ---------------- scratch (device globals) ----------------
__device__ float g_xn[Bb * Nn * Ee];
__device__ float g_q [Bb * Nn * Ll];
__device__ float g_k [Bb * Mm * Ll];
__device__ float g_s [(long)Bb * Nn * Hh * Mm];                  // fp32 scores
__device__ __nv_bfloat16 g_sa [(long)Bb * Nn * KV];              // bf16 softmax probs [(b,n)][h*1024+m]
__device__ __nv_bfloat16 g_vtb[(long)Bb * Ee * KV];              // bf16 v [(b,e)][h*1024+m] (B operand of dx)
__device__ __nv_bfloat16 g_ya [(long)Bb * Mm * Ee];              // bf16 yn [(b,m)][k]
__device__ __nv_bfloat16 g_wb [(long)(Ee * Hh) * Ee];            // bf16 wv [n=9216][k=768] (transposed)
__device__ float g_h [Bb * Nn * Ee];
__device__ float g_hn[Bb * Nn * Ee];
__device__ float g_t [Bb * Nn * Ll];

// ================= helpers =================
__device__ __forceinline__ uint32_t smem_u32(const void* p) {
    uint32_t a;
    asm("{ .reg .u64 t; cvta.to.shared.u64 t, %1; cvt.u32.u64 %0, t; }" : "=r"(a) : "l"(p));
    return a;
}

#define CP_ASYNC16(dst, src) \
    asm volatile("cp.async.cg.shared.global [%0], [%1], 16;" :: "r"(dst), "l"(src))
#define CP_COMMIT() asm volatile("cp.async.commit_group;" ::: "memory")
#define CP_WAIT1()  asm volatile("cp.async.wait_group 1;" ::: "memory")
#define CP_WAIT0()  asm volatile("cp.async.wait_group 0;" ::: "memory")

#define LDSM4(r0, r1, r2, r3, addr) \
    asm volatile("ldmatrix.sync.aligned.m8n8.x4.shared.b16 {%0,%1,%2,%3}, [%4];" \
        : "=r"(r0), "=r"(r1), "=r"(r2), "=r"(r3) : "r"(addr))

#define MMA_BF16(d, a, b) \
    asm volatile("mma.sync.aligned.m16n8k16.row.col.f32.bf16.bf16.f32 " \
        "{%0,%1,%2,%3}, {%4,%5,%6,%7}, {%8,%9}, {%0,%1,%2,%3};" \
        : "+f"((d)[0]), "+f"((d)[1]), "+f"((d)[2]), "+f"((d)[3]) \
        : "r"((a)[0]), "r"((a)[1]), "r"((a)[2]), "r"((a)[3]), "r"((b)[0]), "r"((b)[1]))

// ================= reductions =================
__device__ __forceinline__ float blockReduceSum(float val, float* sbuf) {
    int lane = threadIdx.x & 31, wid = threadIdx.x >> 5;
#pragma unroll
    for (int o = 16; o > 0; o >>= 1) val += __shfl_xor_sync(0xffffffffu, val, o);
    if (lane == 0) sbuf[wid] = val;
    __syncthreads();
    if (wid == 0) {
        float r = (lane < (int)(blockDim.x >> 5)) ? sbuf[lane] : 0.f;
#pragma unroll
        for (int o = 16; o > 0; o >>= 1) r += __shfl_xor_sync(0xffffffffu, r, o);
        if (lane == 0) sbuf[32] = r;
    }
    __syncthreads();
    return sbuf[32];
}
__device__ __forceinline__ float blockReduceMax(float val, float* sbuf) {
    int lane = threadIdx.x & 31, wid = threadIdx.x >> 5;
#pragma unroll
    for (int o = 16; o > 0; o >>= 1) val = fmaxf(val, __shfl_xor_sync(0xffffffffu, val, o));
    if (lane == 0) sbuf[wid] = val;
    __syncthreads();
    if (wid == 0) {
        float r = (lane < (int)(blockDim.x >> 5)) ? sbuf[lane] : -3.4e38f;
#pragma unroll
        for (int o = 16; o > 0; o >>= 1) r = fmaxf(r, __shfl_xor_sync(0xffffffffu, r, o));
        if (lane == 0) sbuf[32] = r;
    }
    __syncthreads();
    return sbuf[32];
}

// ================= LayerNorm =================
__global__ void ln_kernel(const float* __restrict__ x, float* __restrict__ o,
                          const float* __restrict__ g, const float* __restrict__ bt) {
    __shared__ float sbuf[33];
    long row = blockIdx.x;
    const float* p = x + row * Ee;
    int t = threadIdx.x;
    float v0 = p[t], v1 = p[t + 256], v2 = p[t + 512];
    float sum = blockReduceSum(v0 + v1 + v2, sbuf);
    float mean = sum * (1.f / 768.f);
    float d0 = v0 - mean, d1 = v1 - mean, d2 = v2 - mean;
    __syncthreads();
    float sq = blockReduceSum(d0 * d0 + d1 * d1 + d2 * d2, sbuf);
    float rstd = rsqrtf(sq * (1.f / 768.f) + 1e-5f);
    float* q = o + row * Ee;
    q[t]       = d0 * rstd * g[t]       + bt[t];
    q[t + 256] = d1 * rstd * g[t + 256] + bt[t + 256];
    q[t + 512] = d2 * rstd * g[t + 512] + bt[t + 512];
}

// ================= fp32 SGEMM (q, k, MLP) =================
__global__ void __launch_bounds__(256) sgemm_kernel(
    const float* __restrict__ A, const float* __restrict__ Bm, float* __restrict__ C,
    int Ndim, int Kdim, const float* __restrict__ bias, const float* __restrict__ res, int mode)
{
    __shared__ float As[8][128];
    __shared__ float Bs[8][128];
    const int tid = threadIdx.x;
    const int arow = tid >> 1, acol = (tid & 1) * 4;
    const int brl = tid >> 5, bcl = (tid & 31) * 4;
    const int tx = tid & 15, ty = tid >> 4;
    const long arow_g = (long)blockIdx.y * 128 + arow;
    const long bcol_g = (long)blockIdx.x * 128 + bcl;
    const float* Aptr = A + arow_g * Kdim + acol;
    const float* Bptr = Bm + bcol_g;
    float acc[8][8] = {};
    for (int k0 = 0; k0 < Kdim; k0 += 8) {
        float4 a4 = *(const float4*)(Aptr + k0);
        float4 b4 = *(const float4*)(Bptr + (long)(k0 + brl) * Ndim);
        As[acol + 0][arow] = a4.x; As[acol + 1][arow] = a4.y;
        As[acol + 2][arow] = a4.z; As[acol + 3][arow] = a4.w;
        *(float4*)&Bs[brl][bcl] = b4;
        __syncthreads();
#pragma unroll
        for (int kk = 0; kk < 8; kk++) {
            float4 a0 = *(const float4*)&As[kk][ty * 8];
            float4 a1 = *(const float4*)&As[kk][ty * 8 + 4];
            float4 b0 = *(const float4*)&Bs[kk][tx * 8];
            float4 b1 = *(const float4*)&Bs[kk][tx * 8 + 4];
            float ar[8] = {a0.x, a0.y, a0.z, a0.w, a1.x, a1.y, a1.z, a1.w};
            float br[8] = {b0.x, b0.y, b0.z, b0.w, b1.x, b1.y, b1.z, b1.w};
#pragma unroll
            for (int i = 0; i < 8; i++)
#pragma unroll
                for (int j = 0; j < 8; j++)
                    acc[i][j] = fmaf(ar[i], br[j], acc[i][j]);
        }
        __syncthreads();
    }
    const long rowbase = (long)blockIdx.y * 128 + ty * 8;
    const int colbase = blockIdx.x * 128 + tx * 8;
#pragma unroll
    for (int i = 0; i < 8; i++) {
        long row = rowbase + i;
#pragma unroll
        for (int j = 0; j < 8; j++) {
            int col = colbase + j;
            float v = acc[i][j];
            if (bias) v += bias[col];
            if (mode == 1) v = fmaxf(v, 0.f);
            if (mode == 2) v += res[row * Ndim + col];
            C[row * Ndim + col] = v;
        }
    }
}

// ================= scores (K=64, per-head) =================
__global__ void __launch_bounds__(256) scores_kernel(const float* __restrict__ q,
                                                     const float* __restrict__ k,
                                                     float* __restrict__ s)
{
    int bh = blockIdx.z;
    int b = bh / Hh, h = bh - b * Hh;
    int n0 = blockIdx.y * 64, m0 = blockIdx.x * 64;
    const float* qp = q + (long)b * Nn * Ll + h * HDd;
    const float* kp = k + (long)b * Mm * Ll + h * HDd;
    __shared__ float Qs[64][64];
    __shared__ float Ks[64][64];
    int tid = threadIdx.x;
#pragma unroll
    for (int i = 0; i < 4; i++) {
        int idx = tid + i * 256;
        int r = idx >> 4, c4 = (idx & 15) * 4;
        float4 qv = *(const float4*)(qp + (long)(n0 + r) * Ll + c4);
        Qs[c4 + 0][r] = qv.x; Qs[c4 + 1][r] = qv.y;
        Qs[c4 + 2][r] = qv.z; Qs[c4 + 3][r] = qv.w;
        float4 kv = *(const float4*)(kp + (long)(m0 + r) * Ll + c4);
        Ks[c4 + 0][r] = kv.x; Ks[c4 + 1][r] = kv.y;
        Ks[c4 + 2][r] = kv.z; Ks[c4 + 3][r] = kv.w;
    }
    __syncthreads();
    int tx = tid & 15, ty = tid >> 4;
    float acc[4][4] = {};
#pragma unroll
    for (int d = 0; d < 64; d++) {
        float4 a = *(const float4*)&Qs[d][ty * 4];
        float4 bb4 = *(const float4*)&Ks[d][tx * 4];
        float ar[4] = {a.x, a.y, a.z, a.w};
        float br[4] = {bb4.x, bb4.y, bb4.z, bb4.w};
#pragma unroll
        for (int i = 0; i < 4; i++)
#pragma unroll
            for (int j = 0; j < 4; j++)
                acc[i][j] = fmaf(ar[i], br[j], acc[i][j]);
    }
#pragma unroll
    for (int i = 0; i < 4; i++) {
        int n = n0 + ty * 4 + i;
        long base = (((long)b * Nn + n) * Hh + h) * Mm + m0 + tx * 4;
        *(float4*)&s[base] = make_float4(acc[i][0], acc[i][1], acc[i][2], acc[i][3]);
    }
}

// ========== softmax: fp32 in -> bf16 probs out, [(b,n)][h*1024+m] ==========
__global__ void softmax_bf16_kernel(const float* __restrict__ s, __nv_bfloat16* __restrict__ sa) {
    __shared__ float sbuf[33];
    long srow = blockIdx.x;                 // = (b*N + n)*H + h
    const float* p = s + srow * 1024;
    int h  = (int)(srow % Hh);
    long bn = srow / Hh;
    __nv_bfloat16* dst = sa + bn * KV + h * 1024;
    int t = threadIdx.x;
    float4 v = ((const float4*)p)[t];
    const float sc = 0.125f;
    v.x *= sc; v.y *= sc; v.z *= sc; v.w *= sc;
    float mx = blockReduceMax(fmaxf(fmaxf(v.x, v.y), fmaxf(v.z, v.w)), sbuf);
    float e0 = __expf(v.x - mx), e1 = __expf(v.y - mx);
    float e2 = __expf(v.z - mx), e3 = __expf(v.w - mx);
    __syncthreads();
    float sum = blockReduceSum(e0 + e1 + e2 + e3, sbuf);
    float inv = 1.f / sum;
    int m = t * 4;
    *(__nv_bfloat162*)(dst + m)     = __nv_bfloat162(__float2bfloat16(e0 * inv), __float2bfloat16(e1 * inv));
    *(__nv_bfloat162*)(dst + m + 2) = __nv_bfloat162(__float2bfloat16(e2 * inv), __float2bfloat16(e3 * inv));
}

// ========== conv: yn fp32 (rows x 768) -> bf16 (rows x 768) ==========
__global__ void conv_bf16_kernel(const float* __restrict__ in, __nv_bfloat16* __restrict__ out) {
    long row = blockIdx.x;
    int t = threadIdx.x;                    // 192 threads, 4 elems each
    float4 v = ((const float4*)(in + row * Ee))[t];
    __nv_bfloat16* dst = out + row * Ee;
    int k = t * 4;
    *(__nv_bfloat162*)(dst + k)     = __nv_bfloat162(__float2bfloat16(v.x), __float2bfloat16(v.y));
    *(__nv_bfloat162*)(dst + k + 2) = __nv_bfloat162(__float2bfloat16(v.z), __float2bfloat16(v.w));
}

// ========== conv: wv fp32 (768 x 9216) -> bf16 (9216 x 768), transposed ==========
__global__ void conv_wv_kernel(const float* __restrict__ wv, __nv_bfloat16* __restrict__ wb) {
    __shared__ float tile[32][33];
    int k0 = blockIdx.x * 32, n0 = blockIdx.y * 32;
    int tx = threadIdx.x, ty = threadIdx.y;
    tile[ty][tx] = wv[(long)(k0 + ty) * (Ee * Hh) + n0 + tx];
    __syncthreads();
    int n = n0 + ty, k = k0 + tx;
    wb[(long)n * Ee + k] = __float2bfloat16(tile[tx][ty]);
}

// ================= bf16 tensor-core GEMM via mma.sync =================
// C[M,N] = A[M,K'] @ B[N,K']^T ; tile 128x128, K-chunk 32, 8 warps (4m x 2n)
// mode 0: v-proj: D + bias -> bf16 -> scattered transposed writes to Cvt
// mode 1: dx:     D + res  -> fp32 Cf
__global__ void __launch_bounds__(256) gemm_mma_kernel(
    const __nv_bfloat16* __restrict__ A, const __nv_bfloat16* __restrict__ Bm,
    int Kp, long sAb, long sBb,
    const float* __restrict__ bias,
    const float* __restrict__ res, long sRes, float* __restrict__ Cf, long sC, int ldc,
    __nv_bfloat16* __restrict__ Cvt, int mode)
{
    __shared__ alignas(128) __nv_bfloat16 smA[2][128 * 32];
    __shared__ alignas(128) __nv_bfloat16 smB[2][128 * 32];
    const int tid = threadIdx.x, wid = tid >> 5, lane = tid & 31;
    const int bz = blockIdx.z;
    const int n0 = blockIdx.x * 128, m0 = blockIdx.y * 128;
    const __nv_bfloat16* Ap = A + (long)bz * sAb;
    const __nv_bfloat16* Bp = Bm + (long)bz * sBb;

    // ---- staging: thread t<128 loads A row t; t>=128 loads B row t-128.
    const int isA = (tid < 128);
    const int srow = isA ? tid : tid - 128;
    const __nv_bfloat16* gsrc = isA ? (Ap + (long)(m0 + srow) * Kp)
                                    : (Bp + (long)(n0 + srow) * Kp);
    uint32_t sdst0 = smem_u32(isA ? (const void*)&smA[0][0] : (const void*)&smB[0][0]) + srow * 64;
    uint32_t dsw[4];
#pragma unroll
    for (int s2 = 0; s2 < 4; s2++) dsw[s2] = (uint32_t)((s2 ^ ((srow >> 1) & 3)) << 4);

    const int nchunks = Kp >> 5;

    // prefetch chunk 0 -> buf 0
    {
#pragma unroll
        for (int s2 = 0; s2 < 4; s2++) CP_ASYNC16(sdst0 + dsw[s2], gsrc + s2 * 8);
        CP_COMMIT();
    }

    // ---- warp compute indexing
    const int wm = wid & 3, wn = wid >> 2;
    const int lrow = lane & 7;
    int rowA[2], rowB[4];
#pragma unroll
    for (int mt = 0; mt < 2; mt++) rowA[mt] = wm * 32 + mt * 16 + ((lane >> 3) & 1) * 8 + lrow;
#pragma unroll
    for (int np = 0; np < 4; np++) rowB[np] = wn * 64 + np * 16 + (lane >> 4) * 8 + lrow;
    const int segAq = (lane >> 4);
    const int segBq = ((lane >> 3) & 1);
    const uint32_t smA0 = smem_u32(&smA[0][0]);
    const uint32_t smB0 = smem_u32(&smB[0][0]);

    float acc[2][8][4] = {};

    for (int c = 0; c < nchunks; c++) {
        const int buf = c & 1;
        if (c + 1 < nchunks) {
            const __nv_bfloat16* p = gsrc + (long)(c + 1) * 32;
            uint32_t d = sdst0 + (uint32_t)(((c + 1) & 1) * (128 * 32 * 2));
#pragma unroll
            for (int s2 = 0; s2 < 4; s2++) CP_ASYNC16(d + dsw[s2], p + s2 * 8);
            CP_COMMIT();
            CP_WAIT1();
        } else {
            CP_WAIT0();
        }
        __syncthreads();
        const uint32_t aB = smA0 + (uint32_t)(buf * (128 * 32 * 2));
        const uint32_t bB = smB0 + (uint32_t)(buf * (128 * 32 * 2));
#pragma unroll
        for (int ks = 0; ks < 2; ks++) {
            uint32_t aF[2][4];
            uint32_t bF[8][2];
#pragma unroll
            for (int mt = 0; mt < 2; mt++) {
                int row = rowA[mt], seg = ks * 2 + segAq;
                uint32_t ad = aB + row * 64 + (uint32_t)((seg ^ ((row >> 1) & 3)) << 4);
                LDSM4(aF[mt][0], aF[mt][1], aF[mt][2], aF[mt][3], ad);
            }
#pragma unroll
            for (int np = 0; np < 4; np++) {
                int row = rowB[np], seg = ks * 2 + segBq;
                uint32_t bd = bB + row * 64 + (uint32_t)((seg ^ ((row >> 1) & 3)) << 4);
                LDSM4(bF[2 * np][0], bF[2 * np][1], bF[2 * np + 1][0], bF[2 * np + 1][1], bd);
            }
#pragma unroll
            for (int mt = 0; mt < 2; mt++)
#pragma unroll
                for (int nt = 0; nt < 8; nt++)
                    MMA_BF16(acc[mt][nt], aF[mt], bF[nt]);
        }
        __syncthreads();
    }

    // ---- epilogue
    const int r_in = lane >> 2;            // 0..7
    const int c_in = (lane & 3) * 2;       // 0,2,4,6
#pragma unroll
    for (int mt = 0; mt < 2; mt++) {
#pragma unroll
        for (int nt = 0; nt < 8; nt++) {
            int col0 = n0 + wn * 64 + nt * 8 + c_in;
#pragma unroll
            for (int half = 0; half < 2; half++) {
                int row = m0 + wm * 32 + mt * 16 + r_in + half * 8;
                float v0 = acc[mt][nt][half * 2 + 0];
                float v1 = acc[mt][nt][half * 2 + 1];
                if (mode == 1) {
                    const float* rs = res + (long)bz * sRes + (long)row * ldc + col0;
                    float2 rv = *(const float2*)rs;
                    float2 o = make_float2(v0 + rv.x, v1 + rv.y);
                    *(float2*)(Cf + (long)bz * sC + (long)row * ldc + col0) = o;
                } else {
                    int b = row >> 10, m = row & 1023;
#pragma unroll
                    for (int j = 0; j < 2; j++) {
                        int col = col0 + j;
                        float v = (j ? v1 : v0) + bias[col];
                        int h = col / Ee, e = col - h * Ee;
                        long bk = ((long)(b * Ee + e)) * KV + h * 1024 + m;
                        Cvt[bk] = __float2bfloat16(v);
                    }
                }
            }
        }
    }
}

// ================= launch =================
extern "C" void kernel_launch(void* const* d_in, const int* in_sizes, int n_in,
                              void* d_out, int out_size) {
    const float* x     = (const float*)d_in[0];
    const float* y     = (const float*)d_in[1];
    const float* ln1_g = (const float*)d_in[2];
    const float* ln1_b = (const float*)d_in[3];
    const float* ln2_g = (const float*)d_in[4];
    const float* ln2_b = (const float*)d_in[5];
    const float* ln3_g = (const float*)d_in[6];
    const float* ln3_b = (const float*)d_in[7];
    const float* wq    = (const float*)d_in[8];
    const float* bq    = (const float*)d_in[9];
    const float* wk    = (const float*)d_in[10];
    const float* bk    = (const float*)d_in[11];
    const float* wv    = (const float*)d_in[12];
    const float* bv    = (const float*)d_in[13];
    const float* w_in  = (const float*)d_in[14];
    const float* b_in  = (const float*)d_in[15];
    const float* w_out = (const float*)d_in[16];
    const float* b_out = (const float*)d_in[17];

    float* out1 = (float*)d_out;
    float* yn   = out1 + (long)Bb * Nn * Ee;

    float *xn, *qb, *kb, *sb, *hb, *hnb, *tb;
    __nv_bfloat16 *sa, *vtb, *ya, *wb;
    cudaGetSymbolAddress((void**)&xn,  g_xn);
    cudaGetSymbolAddress((void**)&qb,  g_q);
    cudaGetSymbolAddress((void**)&kb,  g_k);
    cudaGetSymbolAddress((void**)&sb,  g_s);
    cudaGetSymbolAddress((void**)&hb,  g_h);
    cudaGetSymbolAddress((void**)&hnb, g_hn);
    cudaGetSymbolAddress((void**)&tb,  g_t);
    cudaGetSymbolAddress((void**)&sa,  g_sa);
    cudaGetSymbolAddress((void**)&vtb, g_vtb);
    cudaGetSymbolAddress((void**)&ya,  g_ya);
    cudaGetSymbolAddress((void**)&wb,  g_wb);

    // 1) LayerNorms
    ln_kernel<<<Bb * Nn, 256>>>(x, xn, ln1_g, ln1_b);
    ln_kernel<<<Bb * Mm, 256>>>(y, yn, ln2_g, ln2_b);

    // 2) conversions for the v-proj tensor GEMM
    conv_bf16_kernel<<<Bb * Mm, 192>>>(yn, ya);
    {
        dim3 blk(32, 32), g(Ee / 32, (Ee * Hh) / 32);
        conv_wv_kernel<<<g, blk>>>(wv, wb);
    }

    // 3) q, k projections (fp32)
    {
        dim3 g(Ll / 128, (Bb * Nn) / 128);
        sgemm_kernel<<<g, 256>>>(xn, wq, qb, Ll, Ee, bq, nullptr, 0);
        sgemm_kernel<<<g, 256>>>(yn, wk, kb, Ll, Ee, bk, nullptr, 0);
    }

    // 4) v projection on tensor cores -> vtB (bf16, [b,e][h*1024+m])
    {
        dim3 g((Ee * Hh) / 128, (Bb * Mm) / 128, 1);
        gemm_mma_kernel<<<g, 256>>>(ya, wb, Ee, 0, 0, bv,
                                    nullptr, 0, nullptr, 0, 0, vtb, 0);
    }

    // 5) scores (fp32)
    {
        dim3 g(Mm / 64, Nn / 64, Bb * Hh);
        scores_kernel<<<g, 256>>>(qb, kb, sb);
    }

    // 6) softmax -> bf16 probs
    softmax_bf16_kernel<<<Bb * Nn * Hh, 256>>>(sb, sa);

    // 7) dx on tensor cores: h = s @ vt + xn
    {
        dim3 g(Ee / 128, Nn / 128, Bb);
        gemm_mma_kernel<<<g, 256>>>(sa, vtb, KV,
                                    (long)Nn * KV, (long)Ee * KV, nullptr,
                                    xn, (long)Nn * Ee, hb, (long)Nn * Ee, Ee,
                                    nullptr, 1);
    }

    // 8) LN3 + MLP (fp32)
    ln_kernel<<<Bb * Nn, 256>>>(hb, hnb, ln3_g, ln3_b);
    {
        dim3 g(Ll / 128, (Bb * Nn) / 128);
        sgemm_kernel<<<g, 256>>>(hnb, w_in, tb, Ll, Ee, b_in, nullptr, 1);
        sgemm_kernel<<<g, 256>>>(tb, w_out, out1, Ee, Ll, b_out, hnb, 2);
    }
}

// round 8
// speedup vs baseline: 2.6859x; 1.0786x over previous
#include <cuda_runtime.h>
#include <cuda_bf16.h>
#include <cstdint>

// Problem constants
#define Ee 768
#define Ll 768
#define Hh 12
#define HDd 64
#define Bb 8
#define Nn 1024
#define Mm 1024
#define KV 12288           // H*M : K of the dx GEMM
#define KE3 2304           // 3*E augmented K for MLP

// ---------------- scratch (device globals) ----------------
__device__ float g_xn[Bb * Nn * Ee];
__device__ float g_s [(long)Bb * Nn * Hh * Mm];                  // fp32 scores
__device__ __nv_bfloat16 g_sa [(long)Bb * Nn * KV];              // bf16 probs [(b,n)][h*1024+m]
__device__ __nv_bfloat16 g_vtb[(long)Bb * Ee * KV];              // bf16 v [(b,e)][h*1024+m]
__device__ __nv_bfloat16 g_xa [Bb * Nn * Ee];                    // bf16 xn
__device__ __nv_bfloat16 g_ya [Bb * Mm * Ee];                    // bf16 yn
__device__ __nv_bfloat16 g_wvt[(long)(Ee * Hh) * Ee];            // bf16 wv^T [9216][768]
__device__ __nv_bfloat16 g_wqt[Ll * Ee];                         // bf16 wq^T [768][768]
__device__ __nv_bfloat16 g_wkt[Ll * Ee];                         // bf16 wk^T [768][768]
__device__ __nv_bfloat16 g_wia[Ll * KE3];                        // aug w_in^T [768][2304]
__device__ __nv_bfloat16 g_woa[Ee * KE3];                        // aug w_out^T [768][2304]
__device__ __nv_bfloat16 g_qbh[(long)Bb * Hh * Nn * HDd];        // q [b][h][n][64]
__device__ __nv_bfloat16 g_kbh[(long)Bb * Hh * Mm * HDd];        // k [b][h][m][64]
__device__ __nv_bfloat16 g_hna[(long)Bb * Nn * KE3];             // aug hn rows [Ah|Ah|Al]
__device__ __nv_bfloat16 g_ta [(long)Bb * Nn * KE3];             // aug relu(t) rows
__device__ float g_h [Bb * Nn * Ee];
__device__ float g_hn[Bb * Nn * Ee];

// ================= helpers =================
__device__ __forceinline__ uint32_t smem_u32(const void* p) {
    uint32_t a;
    asm("{ .reg .u64 t; cvta.to.shared.u64 t, %1; cvt.u32.u64 %0, t; }" : "=r"(a) : "l"(p));
    return a;
}

#define CP_ASYNC16(dst, src) \
    asm volatile("cp.async.cg.shared.global [%0], [%1], 16;" :: "r"(dst), "l"(src))
#define CP_COMMIT() asm volatile("cp.async.commit_group;" ::: "memory")
#define CP_WAIT1()  asm volatile("cp.async.wait_group 1;" ::: "memory")
#define CP_WAIT0()  asm volatile("cp.async.wait_group 0;" ::: "memory")

#define LDSM4(r0, r1, r2, r3, addr) \
    asm volatile("ldmatrix.sync.aligned.m8n8.x4.shared.b16 {%0,%1,%2,%3}, [%4];" \
        : "=r"(r0), "=r"(r1), "=r"(r2), "=r"(r3) : "r"(addr))

#define MMA_BF16(d, a, b) \
    asm volatile("mma.sync.aligned.m16n8k16.row.col.f32.bf16.bf16.f32 " \
        "{%0,%1,%2,%3}, {%4,%5,%6,%7}, {%8,%9}, {%0,%1,%2,%3};" \
        : "+f"((d)[0]), "+f"((d)[1]), "+f"((d)[2]), "+f"((d)[3]) \
        : "r"((a)[0]), "r"((a)[1]), "r"((a)[2]), "r"((a)[3]), "r"((b)[0]), "r"((b)[1]))

// ================= reductions =================
__device__ __forceinline__ float blockReduceSum(float val, float* sbuf) {
    int lane = threadIdx.x & 31, wid = threadIdx.x >> 5;
#pragma unroll
    for (int o = 16; o > 0; o >>= 1) val += __shfl_xor_sync(0xffffffffu, val, o);
    if (lane == 0) sbuf[wid] = val;
    __syncthreads();
    if (wid == 0) {
        float r = (lane < (int)(blockDim.x >> 5)) ? sbuf[lane] : 0.f;
#pragma unroll
        for (int o = 16; o > 0; o >>= 1) r += __shfl_xor_sync(0xffffffffu, r, o);
        if (lane == 0) sbuf[32] = r;
    }
    __syncthreads();
    return sbuf[32];
}
__device__ __forceinline__ float blockReduceMax(float val, float* sbuf) {
    int lane = threadIdx.x & 31, wid = threadIdx.x >> 5;
#pragma unroll
    for (int o = 16; o > 0; o >>= 1) val = fmaxf(val, __shfl_xor_sync(0xffffffffu, val, o));
    if (lane == 0) sbuf[wid] = val;
    __syncthreads();
    if (wid == 0) {
        float r = (lane < (int)(blockDim.x >> 5)) ? sbuf[lane] : -3.4e38f;
#pragma unroll
        for (int o = 16; o > 0; o >>= 1) r = fmaxf(r, __shfl_xor_sync(0xffffffffu, r, o));
        if (lane == 0) sbuf[32] = r;
    }
    __syncthreads();
    return sbuf[32];
}

// ================= LayerNorm variants =================
// fp32 out + plain bf16 out
__global__ void ln_bf16_kernel(const float* __restrict__ x, float* __restrict__ o,
                               __nv_bfloat16* __restrict__ ob,
                               const float* __restrict__ g, const float* __restrict__ bt) {
    __shared__ float sbuf[33];
    long row = blockIdx.x;
    const float* p = x + row * Ee;
    int t = threadIdx.x;
    float v0 = p[t], v1 = p[t + 256], v2 = p[t + 512];
    float sum = blockReduceSum(v0 + v1 + v2, sbuf);
    float mean = sum * (1.f / 768.f);
    float d0 = v0 - mean, d1 = v1 - mean, d2 = v2 - mean;
    __syncthreads();
    float sq = blockReduceSum(d0 * d0 + d1 * d1 + d2 * d2, sbuf);
    float rstd = rsqrtf(sq * (1.f / 768.f) + 1e-5f);
    float r0 = d0 * rstd * g[t]       + bt[t];
    float r1 = d1 * rstd * g[t + 256] + bt[t + 256];
    float r2 = d2 * rstd * g[t + 512] + bt[t + 512];
    float* q = o + row * Ee;
    q[t] = r0; q[t + 256] = r1; q[t + 512] = r2;
    __nv_bfloat16* qb2 = ob + row * Ee;
    qb2[t] = __float2bfloat16(r0);
    qb2[t + 256] = __float2bfloat16(r1);
    qb2[t + 512] = __float2bfloat16(r2);
}

// fp32 out + augmented bf16 rows [Ah|Ah|Al] (2304 wide)
__global__ void ln_aug_kernel(const float* __restrict__ x, float* __restrict__ o,
                              __nv_bfloat16* __restrict__ oa,
                              const float* __restrict__ g, const float* __restrict__ bt) {
    __shared__ float sbuf[33];
    long row = blockIdx.x;
    const float* p = x + row * Ee;
    int t = threadIdx.x;
    float v0 = p[t], v1 = p[t + 256], v2 = p[t + 512];
    float sum = blockReduceSum(v0 + v1 + v2, sbuf);
    float mean = sum * (1.f / 768.f);
    float d0 = v0 - mean, d1 = v1 - mean, d2 = v2 - mean;
    __syncthreads();
    float sq = blockReduceSum(d0 * d0 + d1 * d1 + d2 * d2, sbuf);
    float rstd = rsqrtf(sq * (1.f / 768.f) + 1e-5f);
    float r[3];
    r[0] = d0 * rstd * g[t]       + bt[t];
    r[1] = d1 * rstd * g[t + 256] + bt[t + 256];
    r[2] = d2 * rstd * g[t + 512] + bt[t + 512];
    float* q = o + row * Ee;
    q[t] = r[0]; q[t + 256] = r[1]; q[t + 512] = r[2];
    __nv_bfloat16* qa = oa + row * KE3;
#pragma unroll
    for (int i = 0; i < 3; i++) {
        int pos = t + i * 256;
        __nv_bfloat16 hi = __float2bfloat16(r[i]);
        __nv_bfloat16 lo = __float2bfloat16(r[i] - __bfloat162float(hi));
        qa[pos] = hi; qa[768 + pos] = hi; qa[1536 + pos] = lo;
    }
}

// ========== weight transpose convs ==========
// src fp32 [768 k][ncols n] -> dst bf16 [n][768 k]
__global__ void conv_wt_kernel(const float* __restrict__ w, __nv_bfloat16* __restrict__ wt, int ncols) {
    __shared__ float tile[32][33];
    int k0 = blockIdx.x * 32, n0 = blockIdx.y * 32;
    int tx = threadIdx.x, ty = threadIdx.y;
    tile[ty][tx] = w[(long)(k0 + ty) * ncols + n0 + tx];
    __syncthreads();
    int n = n0 + ty, k = k0 + tx;
    wt[(long)n * Ee + k] = __float2bfloat16(tile[tx][ty]);
}

// src fp32 [768 k][768 n] -> dst aug bf16 [n][2304] as [Bh;Bl;Bh]
__global__ void conv_wt_aug_kernel(const float* __restrict__ w, __nv_bfloat16* __restrict__ wt) {
    __shared__ float tile[32][33];
    int k0 = blockIdx.x * 32, n0 = blockIdx.y * 32;
    int tx = threadIdx.x, ty = threadIdx.y;
    tile[ty][tx] = w[(long)(k0 + ty) * Ee + n0 + tx];
    __syncthreads();
    int n = n0 + ty, k = k0 + tx;
    float v = tile[tx][ty];
    __nv_bfloat16 hi = __float2bfloat16(v);
    __nv_bfloat16 lo = __float2bfloat16(v - __bfloat162float(hi));
    __nv_bfloat16* dst = wt + (long)n * KE3;
    dst[k] = hi; dst[768 + k] = lo; dst[1536 + k] = hi;
}

// ========== softmax: fp32 in -> bf16 probs out, [(b,n)][h*1024+m] ==========
__global__ void softmax_bf16_kernel(const float* __restrict__ s, __nv_bfloat16* __restrict__ sa) {
    __shared__ float sbuf[33];
    long srow = blockIdx.x;                 // = (b*N + n)*H + h
    const float* p = s + srow * 1024;
    int h  = (int)(srow % Hh);
    long bn = srow / Hh;
    __nv_bfloat16* dst = sa + bn * KV + h * 1024;
    int t = threadIdx.x;
    float4 v = ((const float4*)p)[t];
    const float sc = 0.125f;
    v.x *= sc; v.y *= sc; v.z *= sc; v.w *= sc;
    float mx = blockReduceMax(fmaxf(fmaxf(v.x, v.y), fmaxf(v.z, v.w)), sbuf);
    float e0 = __expf(v.x - mx), e1 = __expf(v.y - mx);
    float e2 = __expf(v.z - mx), e3 = __expf(v.w - mx);
    __syncthreads();
    float sum = blockReduceSum(e0 + e1 + e2 + e3, sbuf);
    float inv = 1.f / sum;
    int m = t * 4;
    *(__nv_bfloat162*)(dst + m)     = __nv_bfloat162(__float2bfloat16(e0 * inv), __float2bfloat16(e1 * inv));
    *(__nv_bfloat162*)(dst + m + 2) = __nv_bfloat162(__float2bfloat16(e2 * inv), __float2bfloat16(e3 * inv));
}

// ================= bf16 tensor-core GEMM via mma.sync =================
// C[M,N] = A[M,K'] @ B[N,K']^T ; tile 128x128, K-chunk 32, 8 warps (4m x 2n)
// mode 0: v-proj scatter: bf16(acc+bias) -> Cvt[(b*E+e)*KV + h*1024+m]
// mode 1: fp32 out = acc (+bias) + res
// mode 2: q/k scatter: bf16(acc+bias) -> Cvt[((b*H+h)*1024+n)*64+d]
// mode 3: scores: fp32 acc -> Cf[((b*1024+row)*KV) + h*1024+col], b,h from bz
// mode 4: relu-aug rows: v=relu(acc+bias); Cvt[row*2304+{col,768+col}]=hi, [1536+col]=lo
__global__ void __launch_bounds__(256) gemm_mma_kernel(
    const __nv_bfloat16* __restrict__ A, const __nv_bfloat16* __restrict__ Bm,
    int Kp, long sAb, long sBb,
    const float* __restrict__ bias,
    const float* __restrict__ res, long sRes, float* __restrict__ Cf, long sC, int ldc,
    __nv_bfloat16* __restrict__ Cvt, int mode)
{
    __shared__ alignas(128) __nv_bfloat16 smA[2][128 * 32];
    __shared__ alignas(128) __nv_bfloat16 smB[2][128 * 32];
    const int tid = threadIdx.x, wid = tid >> 5, lane = tid & 31;
    const int bz = blockIdx.z;
    const int n0 = blockIdx.x * 128, m0 = blockIdx.y * 128;
    const __nv_bfloat16* Ap = A + (long)bz * sAb;
    const __nv_bfloat16* Bp = Bm + (long)bz * sBb;

    // ---- staging: thread t<128 loads A row t; t>=128 loads B row t-128.
    const int isA = (tid < 128);
    const int srow = isA ? tid : tid - 128;
    const __nv_bfloat16* gsrc = isA ? (Ap + (long)(m0 + srow) * Kp)
                                    : (Bp + (long)(n0 + srow) * Kp);
    uint32_t sdst0 = smem_u32(isA ? (const void*)&smA[0][0] : (const void*)&smB[0][0]) + srow * 64;
    uint32_t dsw[4];
#pragma unroll
    for (int s2 = 0; s2 < 4; s2++) dsw[s2] = (uint32_t)((s2 ^ ((srow >> 1) & 3)) << 4);

    const int nchunks = Kp >> 5;

    // prefetch chunk 0 -> buf 0
    {
#pragma unroll
        for (int s2 = 0; s2 < 4; s2++) CP_ASYNC16(sdst0 + dsw[s2], gsrc + s2 * 8);
        CP_COMMIT();
    }

    // ---- warp compute indexing
    const int wm = wid & 3, wn = wid >> 2;
    const int lrow = lane & 7;
    int rowA[2], rowB[4];
#pragma unroll
    for (int mt = 0; mt < 2; mt++) rowA[mt] = wm * 32 + mt * 16 + ((lane >> 3) & 1) * 8 + lrow;
#pragma unroll
    for (int np = 0; np < 4; np++) rowB[np] = wn * 64 + np * 16 + (lane >> 4) * 8 + lrow;
    const int segAq = (lane >> 4);
    const int segBq = ((lane >> 3) & 1);
    const uint32_t smA0 = smem_u32(&smA[0][0]);
    const uint32_t smB0 = smem_u32(&smB[0][0]);

    float acc[2][8][4] = {};

    for (int c = 0; c < nchunks; c++) {
        const int buf = c & 1;
        if (c + 1 < nchunks) {
            const __nv_bfloat16* p = gsrc + (long)(c + 1) * 32;
            uint32_t d = sdst0 + (uint32_t)(((c + 1) & 1) * (128 * 32 * 2));
#pragma unroll
            for (int s2 = 0; s2 < 4; s2++) CP_ASYNC16(d + dsw[s2], p + s2 * 8);
            CP_COMMIT();
            CP_WAIT1();
        } else {
            CP_WAIT0();
        }
        __syncthreads();
        const uint32_t aB = smA0 + (uint32_t)(buf * (128 * 32 * 2));
        const uint32_t bB = smB0 + (uint32_t)(buf * (128 * 32 * 2));
#pragma unroll
        for (int ks = 0; ks < 2; ks++) {
            uint32_t aF[2][4];
            uint32_t bF[8][2];
#pragma unroll
            for (int mt = 0; mt < 2; mt++) {
                int row = rowA[mt], seg = ks * 2 + segAq;
                uint32_t ad = aB + row * 64 + (uint32_t)((seg ^ ((row >> 1) & 3)) << 4);
                LDSM4(aF[mt][0], aF[mt][1], aF[mt][2], aF[mt][3], ad);
            }
#pragma unroll
            for (int np = 0; np < 4; np++) {
                int row = rowB[np], seg = ks * 2 + segBq;
                uint32_t bd = bB + row * 64 + (uint32_t)((seg ^ ((row >> 1) & 3)) << 4);
                LDSM4(bF[2 * np][0], bF[2 * np][1], bF[2 * np + 1][0], bF[2 * np + 1][1], bd);
            }
#pragma unroll
            for (int mt = 0; mt < 2; mt++)
#pragma unroll
                for (int nt = 0; nt < 8; nt++)
                    MMA_BF16(acc[mt][nt], aF[mt], bF[nt]);
        }
        __syncthreads();
    }

    // ---- epilogue
    const int r_in = lane >> 2;            // 0..7
    const int c_in = (lane & 3) * 2;       // 0,2,4,6
#pragma unroll
    for (int mt = 0; mt < 2; mt++) {
#pragma unroll
        for (int nt = 0; nt < 8; nt++) {
            int col0 = n0 + wn * 64 + nt * 8 + c_in;
#pragma unroll
            for (int half = 0; half < 2; half++) {
                int row = m0 + wm * 32 + mt * 16 + r_in + half * 8;
                float v0 = acc[mt][nt][half * 2 + 0];
                float v1 = acc[mt][nt][half * 2 + 1];
                if (mode == 1) {
                    if (bias) { v0 += bias[col0]; v1 += bias[col0 + 1]; }
                    const float* rs = res + (long)bz * sRes + (long)row * ldc + col0;
                    float2 rv = *(const float2*)rs;
                    *(float2*)(Cf + (long)bz * sC + (long)row * ldc + col0) = make_float2(v0 + rv.x, v1 + rv.y);
                } else if (mode == 3) {
                    int b = bz / Hh, h = bz - b * Hh;
                    long addr = ((long)b * 1024 + row) * KV + h * 1024 + col0;
                    *(float2*)(Cf + addr) = make_float2(v0, v1);
                } else if (mode == 0) {
                    int b = row >> 10, m = row & 1023;
                    v0 += bias[col0]; v1 += bias[col0 + 1];
                    int h = col0 / Ee, e = col0 - h * Ee;   // col pairs stay in same h except at e=767 (col0 even -> safe)
                    long bk = ((long)(b * Ee + e)) * KV + h * 1024 + m;
                    Cvt[bk] = __float2bfloat16(v0);
                    int h1 = (col0 + 1) / Ee, e1 = (col0 + 1) - h1 * Ee;
                    long bk1 = ((long)(b * Ee + e1)) * KV + h1 * 1024 + m;
                    Cvt[bk1] = __float2bfloat16(v1);
                } else if (mode == 2) {
                    int b = row >> 10, n = row & 1023;
                    v0 += bias[col0]; v1 += bias[col0 + 1];
                    int h = col0 >> 6, d = col0 & 63;       // d even -> pair within same head
                    long addr = (((long)(b * Hh + h) * 1024 + n) << 6) + d;
                    *(__nv_bfloat162*)(Cvt + addr) = __nv_bfloat162(__float2bfloat16(v0), __float2bfloat16(v1));
                } else { // mode 4
                    v0 = fmaxf(v0 + bias[col0], 0.f);
                    v1 = fmaxf(v1 + bias[col0 + 1], 0.f);
                    __nv_bfloat16 h0 = __float2bfloat16(v0), h1b = __float2bfloat16(v1);
                    __nv_bfloat16 l0 = __float2bfloat16(v0 - __bfloat162float(h0));
                    __nv_bfloat16 l1 = __float2bfloat16(v1 - __bfloat162float(h1b));
                    __nv_bfloat16* dst = Cvt + (long)row * KE3;
                    __nv_bfloat162 hp = __nv_bfloat162(h0, h1b);
                    *(__nv_bfloat162*)(dst + col0) = hp;
                    *(__nv_bfloat162*)(dst + 768 + col0) = hp;
                    *(__nv_bfloat162*)(dst + 1536 + col0) = __nv_bfloat162(l0, l1);
                }
            }
        }
    }
}

// ================= launch =================
extern "C" void kernel_launch(void* const* d_in, const int* in_sizes, int n_in,
                              void* d_out, int out_size) {
    const float* x     = (const float*)d_in[0];
    const float* y     = (const float*)d_in[1];
    const float* ln1_g = (const float*)d_in[2];
    const float* ln1_b = (const float*)d_in[3];
    const float* ln2_g = (const float*)d_in[4];
    const float* ln2_b = (const float*)d_in[5];
    const float* ln3_g = (const float*)d_in[6];
    const float* ln3_b = (const float*)d_in[7];
    const float* wq    = (const float*)d_in[8];
    const float* bq    = (const float*)d_in[9];
    const float* wk    = (const float*)d_in[10];
    const float* bk    = (const float*)d_in[11];
    const float* wv    = (const float*)d_in[12];
    const float* bv    = (const float*)d_in[13];
    const float* w_in  = (const float*)d_in[14];
    const float* b_in  = (const float*)d_in[15];
    const float* w_out = (const float*)d_in[16];
    const float* b_out = (const float*)d_in[17];

    float* out1 = (float*)d_out;
    float* yn   = out1 + (long)Bb * Nn * Ee;

    float *xn, *sb, *hb, *hnb;
    __nv_bfloat16 *sa, *vtb, *xa, *ya, *wvt, *wqt, *wkt, *wia, *woa, *qbh, *kbh, *hna, *ta;
    cudaGetSymbolAddress((void**)&xn,  g_xn);
    cudaGetSymbolAddress((void**)&sb,  g_s);
    cudaGetSymbolAddress((void**)&hb,  g_h);
    cudaGetSymbolAddress((void**)&hnb, g_hn);
    cudaGetSymbolAddress((void**)&sa,  g_sa);
    cudaGetSymbolAddress((void**)&vtb, g_vtb);
    cudaGetSymbolAddress((void**)&xa,  g_xa);
    cudaGetSymbolAddress((void**)&ya,  g_ya);
    cudaGetSymbolAddress((void**)&wvt, g_wvt);
    cudaGetSymbolAddress((void**)&wqt, g_wqt);
    cudaGetSymbolAddress((void**)&wkt, g_wkt);
    cudaGetSymbolAddress((void**)&wia, g_wia);
    cudaGetSymbolAddress((void**)&woa, g_woa);
    cudaGetSymbolAddress((void**)&qbh, g_qbh);
    cudaGetSymbolAddress((void**)&kbh, g_kbh);
    cudaGetSymbolAddress((void**)&hna, g_hna);
    cudaGetSymbolAddress((void**)&ta,  g_ta);

    // 1) LayerNorms (fp32 + bf16 copies)
    ln_bf16_kernel<<<Bb * Nn, 256>>>(x, xn, xa, ln1_g, ln1_b);
    ln_bf16_kernel<<<Bb * Mm, 256>>>(y, yn, ya, ln2_g, ln2_b);

    // 2) weight conversions
    {
        dim3 blk(32, 32);
        conv_wt_kernel<<<dim3(24, 288), blk>>>(wv, wvt, Ee * Hh);
        conv_wt_kernel<<<dim3(24, 24), blk>>>(wq, wqt, Ll);
        conv_wt_kernel<<<dim3(24, 24), blk>>>(wk, wkt, Ll);
        conv_wt_aug_kernel<<<dim3(24, 24), blk>>>(w_in, wia);
        conv_wt_aug_kernel<<<dim3(24, 24), blk>>>(w_out, woa);
    }

    // 3) q, k projections (bf16 mma) -> q/k in [b][h][n][64]
    {
        dim3 g(Ll / 128, (Bb * Nn) / 128);
        gemm_mma_kernel<<<g, 256>>>(xa, wqt, Ee, 0, 0, bq, nullptr, 0, nullptr, 0, 0, qbh, 2);
        gemm_mma_kernel<<<g, 256>>>(ya, wkt, Ee, 0, 0, bk, nullptr, 0, nullptr, 0, 0, kbh, 2);
    }

    // 4) v projection (bf16 mma) -> vtB [(b,e)][h*1024+m]
    {
        dim3 g((Ee * Hh) / 128, (Bb * Mm) / 128);
        gemm_mma_kernel<<<g, 256>>>(ya, wvt, Ee, 0, 0, bv, nullptr, 0, nullptr, 0, 0, vtb, 0);
    }

    // 5) scores (bf16 mma, K=64): s[b,n,h,m]
    {
        dim3 g(Mm / 128, Nn / 128, Bb * Hh);
        gemm_mma_kernel<<<g, 256>>>(qbh, kbh, HDd, (long)Nn * HDd, (long)Mm * HDd,
                                    nullptr, nullptr, 0, sb, 0, 0, nullptr, 3);
    }

    // 6) softmax -> bf16 probs
    softmax_bf16_kernel<<<Bb * Nn * Hh, 256>>>(sb, sa);

    // 7) dx (bf16 mma): h = s @ vt + xn
    {
        dim3 g(Ee / 128, Nn / 128, Bb);
        gemm_mma_kernel<<<g, 256>>>(sa, vtb, KV,
                                    (long)Nn * KV, (long)Ee * KV, nullptr,
                                    xn, (long)Nn * Ee, hb, (long)Nn * Ee, Ee,
                                    nullptr, 1);
    }

    // 8) LN3 (fp32 + aug bf16 rows)
    ln_aug_kernel<<<Bb * Nn, 256>>>(hb, hnb, hna, ln3_g, ln3_b);

    // 9) MLP (x3-augmented bf16 mma): t = relu(hn@w_in+b_in); out1 = hn + t@w_out + b_out
    {
        dim3 g(Ll / 128, (Bb * Nn) / 128);
        gemm_mma_kernel<<<g, 256>>>(hna, wia, KE3, 0, 0, b_in, nullptr, 0, nullptr, 0, 0, ta, 4);
        gemm_mma_kernel<<<g, 256>>>(ta, woa, KE3, 0, 0, b_out, hnb, 0, out1, 0, Ee, nullptr, 1);
    }
}

// round 9
// speedup vs baseline: 4.2839x; 1.5950x over previous
#include <cuda_runtime.h>
#include <cuda_bf16.h>
#include <cstdint>

// Problem constants
#define Ee 768
#define Ll 768
#define Hh 12
#define HDd 64
#define Bb 8
#define Nn 1024
#define Mm 1024
#define KV 12288           // H*M : K of the dx GEMM
#define KE3 2304           // 3*E augmented K for MLP

// ---------------- scratch (device globals) ----------------
__device__ float g_xn[Bb * Nn * Ee];
__device__ float g_s [(long)Bb * Nn * Hh * Mm];                  // fp32 scores
__device__ __nv_bfloat16 g_sa [(long)Bb * Nn * KV];              // bf16 probs [(b,n)][h*1024+m]
__device__ __nv_bfloat16 g_vtb[(long)Bb * Ee * KV];              // bf16 v [(b,e)][h*1024+m]
__device__ __nv_bfloat16 g_xa [Bb * Nn * Ee];                    // bf16 xn
__device__ __nv_bfloat16 g_ya [Bb * Mm * Ee];                    // bf16 yn
__device__ __nv_bfloat16 g_wvt[(long)(Ee * Hh) * Ee];            // bf16 wv^T [9216][768]
__device__ __nv_bfloat16 g_wqt[Ll * Ee];                         // bf16 wq^T
__device__ __nv_bfloat16 g_wkt[Ll * Ee];                         // bf16 wk^T
__device__ __nv_bfloat16 g_wia[Ll * KE3];                        // aug w_in^T [768][2304]
__device__ __nv_bfloat16 g_woa[Ee * KE3];                        // aug w_out^T [768][2304]
__device__ __nv_bfloat16 g_qbh[(long)Bb * Hh * Nn * HDd];        // q [b][h][n][64]
__device__ __nv_bfloat16 g_kbh[(long)Bb * Hh * Mm * HDd];        // k [b][h][m][64]
__device__ __nv_bfloat16 g_hna[(long)Bb * Nn * KE3];             // aug hn rows [Ah|Ah|Al]
__device__ __nv_bfloat16 g_ta [(long)Bb * Nn * KE3];             // aug relu(t) rows
__device__ float g_h [Bb * Nn * Ee];
__device__ float g_hn[Bb * Nn * Ee];

// ================= helpers =================
__device__ __forceinline__ uint32_t smem_u32(const void* p) {
    uint32_t a;
    asm("{ .reg .u64 t; cvta.to.shared.u64 t, %1; cvt.u32.u64 %0, t; }" : "=r"(a) : "l"(p));
    return a;
}

#define CP_ASYNC16(dst, src) \
    asm volatile("cp.async.cg.shared.global [%0], [%1], 16;" :: "r"(dst), "l"(src))
#define CP_COMMIT() asm volatile("cp.async.commit_group;" ::: "memory")
#define CP_WAIT1()  asm volatile("cp.async.wait_group 1;" ::: "memory")
#define CP_WAIT0()  asm volatile("cp.async.wait_group 0;" ::: "memory")

#define LDSM4(r0, r1, r2, r3, addr) \
    asm volatile("ldmatrix.sync.aligned.m8n8.x4.shared.b16 {%0,%1,%2,%3}, [%4];" \
        : "=r"(r0), "=r"(r1), "=r"(r2), "=r"(r3) : "r"(addr))

#define MMA_BF16(d, a, b) \
    asm volatile("mma.sync.aligned.m16n8k16.row.col.f32.bf16.bf16.f32 " \
        "{%0,%1,%2,%3}, {%4,%5,%6,%7}, {%8,%9}, {%0,%1,%2,%3};" \
        : "+f"((d)[0]), "+f"((d)[1]), "+f"((d)[2]), "+f"((d)[3]) \
        : "r"((a)[0]), "r"((a)[1]), "r"((a)[2]), "r"((a)[3]), "r"((b)[0]), "r"((b)[1]))

// ================= reductions =================
__device__ __forceinline__ float blockReduceSum(float val, float* sbuf) {
    int lane = threadIdx.x & 31, wid = threadIdx.x >> 5;
#pragma unroll
    for (int o = 16; o > 0; o >>= 1) val += __shfl_xor_sync(0xffffffffu, val, o);
    if (lane == 0) sbuf[wid] = val;
    __syncthreads();
    if (wid == 0) {
        float r = (lane < (int)(blockDim.x >> 5)) ? sbuf[lane] : 0.f;
#pragma unroll
        for (int o = 16; o > 0; o >>= 1) r += __shfl_xor_sync(0xffffffffu, r, o);
        if (lane == 0) sbuf[32] = r;
    }
    __syncthreads();
    return sbuf[32];
}
__device__ __forceinline__ float blockReduceMax(float val, float* sbuf) {
    int lane = threadIdx.x & 31, wid = threadIdx.x >> 5;
#pragma unroll
    for (int o = 16; o > 0; o >>= 1) val = fmaxf(val, __shfl_xor_sync(0xffffffffu, val, o));
    if (lane == 0) sbuf[wid] = val;
    __syncthreads();
    if (wid == 0) {
        float r = (lane < (int)(blockDim.x >> 5)) ? sbuf[lane] : -3.4e38f;
#pragma unroll
        for (int o = 16; o > 0; o >>= 1) r = fmaxf(r, __shfl_xor_sync(0xffffffffu, r, o));
        if (lane == 0) sbuf[32] = r;
    }
    __syncthreads();
    return sbuf[32];
}

// ================= LayerNorm variants =================
__global__ void ln_bf16_kernel(const float* __restrict__ x, float* __restrict__ o,
                               __nv_bfloat16* __restrict__ ob,
                               const float* __restrict__ g, const float* __restrict__ bt) {
    __shared__ float sbuf[33];
    long row = blockIdx.x;
    const float* p = x + row * Ee;
    int t = threadIdx.x;
    float v0 = p[t], v1 = p[t + 256], v2 = p[t + 512];
    float sum = blockReduceSum(v0 + v1 + v2, sbuf);
    float mean = sum * (1.f / 768.f);
    float d0 = v0 - mean, d1 = v1 - mean, d2 = v2 - mean;
    __syncthreads();
    float sq = blockReduceSum(d0 * d0 + d1 * d1 + d2 * d2, sbuf);
    float rstd = rsqrtf(sq * (1.f / 768.f) + 1e-5f);
    float r0 = d0 * rstd * g[t]       + bt[t];
    float r1 = d1 * rstd * g[t + 256] + bt[t + 256];
    float r2 = d2 * rstd * g[t + 512] + bt[t + 512];
    float* q = o + row * Ee;
    q[t] = r0; q[t + 256] = r1; q[t + 512] = r2;
    __nv_bfloat16* qb2 = ob + row * Ee;
    qb2[t] = __float2bfloat16(r0);
    qb2[t + 256] = __float2bfloat16(r1);
    qb2[t + 512] = __float2bfloat16(r2);
}

__global__ void ln_aug_kernel(const float* __restrict__ x, float* __restrict__ o,
                              __nv_bfloat16* __restrict__ oa,
                              const float* __restrict__ g, const float* __restrict__ bt) {
    __shared__ float sbuf[33];
    long row = blockIdx.x;
    const float* p = x + row * Ee;
    int t = threadIdx.x;
    float v0 = p[t], v1 = p[t + 256], v2 = p[t + 512];
    float sum = blockReduceSum(v0 + v1 + v2, sbuf);
    float mean = sum * (1.f / 768.f);
    float d0 = v0 - mean, d1 = v1 - mean, d2 = v2 - mean;
    __syncthreads();
    float sq = blockReduceSum(d0 * d0 + d1 * d1 + d2 * d2, sbuf);
    float rstd = rsqrtf(sq * (1.f / 768.f) + 1e-5f);
    float r[3];
    r[0] = d0 * rstd * g[t]       + bt[t];
    r[1] = d1 * rstd * g[t + 256] + bt[t + 256];
    r[2] = d2 * rstd * g[t + 512] + bt[t + 512];
    float* q = o + row * Ee;
    q[t] = r[0]; q[t + 256] = r[1]; q[t + 512] = r[2];
    __nv_bfloat16* qa = oa + row * KE3;
#pragma unroll
    for (int i = 0; i < 3; i++) {
        int pos = t + i * 256;
        __nv_bfloat16 hi = __float2bfloat16(r[i]);
        __nv_bfloat16 lo = __float2bfloat16(r[i] - __bfloat162float(hi));
        qa[pos] = hi; qa[768 + pos] = hi; qa[1536 + pos] = lo;
    }
}

// ========== weight transpose convs ==========
__global__ void conv_wt_kernel(const float* __restrict__ w, __nv_bfloat16* __restrict__ wt, int ncols) {
    __shared__ float tile[32][33];
    int k0 = blockIdx.x * 32, n0 = blockIdx.y * 32;
    int tx = threadIdx.x, ty = threadIdx.y;
    tile[ty][tx] = w[(long)(k0 + ty) * ncols + n0 + tx];
    __syncthreads();
    int n = n0 + ty, k = k0 + tx;
    wt[(long)n * Ee + k] = __float2bfloat16(tile[tx][ty]);
}

__global__ void conv_wt_aug_kernel(const float* __restrict__ w, __nv_bfloat16* __restrict__ wt) {
    __shared__ float tile[32][33];
    int k0 = blockIdx.x * 32, n0 = blockIdx.y * 32;
    int tx = threadIdx.x, ty = threadIdx.y;
    tile[ty][tx] = w[(long)(k0 + ty) * Ee + n0 + tx];
    __syncthreads();
    int n = n0 + ty, k = k0 + tx;
    float v = tile[tx][ty];
    __nv_bfloat16 hi = __float2bfloat16(v);
    __nv_bfloat16 lo = __float2bfloat16(v - __bfloat162float(hi));
    __nv_bfloat16* dst = wt + (long)n * KE3;
    dst[k] = hi; dst[768 + k] = lo; dst[1536 + k] = hi;
}

// ========== softmax: fp32 in -> bf16 probs out, [(b,n)][h*1024+m] ==========
__global__ void softmax_bf16_kernel(const float* __restrict__ s, __nv_bfloat16* __restrict__ sa) {
    __shared__ float sbuf[33];
    long srow = blockIdx.x;                 // = (b*N + n)*H + h
    const float* p = s + srow * 1024;
    int h  = (int)(srow % Hh);
    long bn = srow / Hh;
    __nv_bfloat16* dst = sa + bn * KV + h * 1024;
    int t = threadIdx.x;
    float4 v = ((const float4*)p)[t];
    const float sc = 0.125f;
    v.x *= sc; v.y *= sc; v.z *= sc; v.w *= sc;
    float mx = blockReduceMax(fmaxf(fmaxf(v.x, v.y), fmaxf(v.z, v.w)), sbuf);
    float e0 = __expf(v.x - mx), e1 = __expf(v.y - mx);
    float e2 = __expf(v.z - mx), e3 = __expf(v.w - mx);
    __syncthreads();
    float sum = blockReduceSum(e0 + e1 + e2 + e3, sbuf);
    float inv = 1.f / sum;
    int m = t * 4;
    *(__nv_bfloat162*)(dst + m)     = __nv_bfloat162(__float2bfloat16(e0 * inv), __float2bfloat16(e1 * inv));
    *(__nv_bfloat162*)(dst + m + 2) = __nv_bfloat162(__float2bfloat16(e2 * inv), __float2bfloat16(e3 * inv));
}

// ================= bf16 tensor-core GEMM via mma.sync =================
// 3-stage cp.async pipeline, one __syncthreads per 32-K chunk.
// mode 0: v-proj: smem-transposed coalesced bf16 writes to Cvt[(b*E+e)*KV + h*1024+m]
// mode 1: fp32 out = acc (+bias) + res
// mode 2: q/k scatter: bf16(acc+bias) -> Cvt[((b*H+h)*1024+n)*64+d]
// mode 3: scores: fp32 acc -> Cf[(b*1024+row)*KV + h*1024+col]
// mode 4: relu-aug rows -> Cvt[row*2304 + {col, 768+col}]=hi, [1536+col]=lo
#define TRS 136   // transpose smem stride (bf16 units), 272B: 16B-aligned cols
__global__ void __launch_bounds__(256) gemm_mma_kernel(
    const __nv_bfloat16* __restrict__ A, const __nv_bfloat16* __restrict__ Bm,
    int Kp, long sAb, long sBb,
    const float* __restrict__ bias,
    const float* __restrict__ res, long sRes, float* __restrict__ Cf, long sC, int ldc,
    __nv_bfloat16* __restrict__ Cvt, int mode)
{
    __shared__ union {
        struct { __nv_bfloat16 A[3][128 * 32]; __nv_bfloat16 B[3][128 * 32]; } p;
        __nv_bfloat16 tr[128 * TRS];
    } sm;
    const int tid = threadIdx.x, wid = tid >> 5, lane = tid & 31;
    const int bz = blockIdx.z;
    const int n0 = blockIdx.x * 128, m0 = blockIdx.y * 128;
    const __nv_bfloat16* Ap = A + (long)bz * sAb;
    const __nv_bfloat16* Bp = Bm + (long)bz * sBb;

    // ---- staging: thread t<128 loads A row t; t>=128 loads B row t-128.
    const int isA = (tid < 128);
    const int srow = isA ? tid : tid - 128;
    const __nv_bfloat16* gsrc = isA ? (Ap + (long)(m0 + srow) * Kp)
                                    : (Bp + (long)(n0 + srow) * Kp);
    uint32_t stage0 = smem_u32(isA ? (const void*)&sm.p.A[0][0] : (const void*)&sm.p.B[0][0]) + srow * 64;
    uint32_t dsw[4];
#pragma unroll
    for (int s2 = 0; s2 < 4; s2++) dsw[s2] = (uint32_t)((s2 ^ ((srow >> 1) & 3)) << 4);

    const int nchunks = Kp >> 5;

    // prefetch chunks 0,1
#pragma unroll
    for (int pc = 0; pc < 2; pc++) {
        if (pc < nchunks) {
            uint32_t d = stage0 + (uint32_t)(pc * 8192);
            const __nv_bfloat16* p = gsrc + (long)pc * 32;
#pragma unroll
            for (int s2 = 0; s2 < 4; s2++) CP_ASYNC16(d + dsw[s2], p + s2 * 8);
            CP_COMMIT();
        }
    }

    // ---- warp compute indexing
    const int wm = wid & 3, wn = wid >> 2;
    const int lrow = lane & 7;
    int rowA[2], rowB[4];
#pragma unroll
    for (int mt = 0; mt < 2; mt++) rowA[mt] = wm * 32 + mt * 16 + ((lane >> 3) & 1) * 8 + lrow;
#pragma unroll
    for (int np = 0; np < 4; np++) rowB[np] = wn * 64 + np * 16 + (lane >> 4) * 8 + lrow;
    const int segAq = (lane >> 4);
    const int segBq = ((lane >> 3) & 1);
    const uint32_t smA0 = smem_u32(&sm.p.A[0][0]);
    const uint32_t smB0 = smem_u32(&sm.p.B[0][0]);

    float acc[2][8][4] = {};

    for (int c = 0; c < nchunks; c++) {
        if (c + 1 < nchunks) { CP_WAIT1(); } else { CP_WAIT0(); }
        __syncthreads();
        if (c + 2 < nchunks) {
            const int st = (c + 2) % 3;
            uint32_t d = stage0 + (uint32_t)(st * 8192);
            const __nv_bfloat16* p = gsrc + (long)(c + 2) * 32;
#pragma unroll
            for (int s2 = 0; s2 < 4; s2++) CP_ASYNC16(d + dsw[s2], p + s2 * 8);
            CP_COMMIT();
        }
        const int buf = c % 3;
        const uint32_t aB = smA0 + (uint32_t)(buf * 8192);
        const uint32_t bB = smB0 + (uint32_t)(buf * 8192);
#pragma unroll
        for (int ks = 0; ks < 2; ks++) {
            uint32_t aF[2][4];
            uint32_t bF[8][2];
#pragma unroll
            for (int mt = 0; mt < 2; mt++) {
                int row = rowA[mt], seg = ks * 2 + segAq;
                uint32_t ad = aB + row * 64 + (uint32_t)((seg ^ ((row >> 1) & 3)) << 4);
                LDSM4(aF[mt][0], aF[mt][1], aF[mt][2], aF[mt][3], ad);
            }
#pragma unroll
            for (int np = 0; np < 4; np++) {
                int row = rowB[np], seg = ks * 2 + segBq;
                uint32_t bd = bB + row * 64 + (uint32_t)((seg ^ ((row >> 1) & 3)) << 4);
                LDSM4(bF[2 * np][0], bF[2 * np][1], bF[2 * np + 1][0], bF[2 * np + 1][1], bd);
            }
#pragma unroll
            for (int mt = 0; mt < 2; mt++)
#pragma unroll
                for (int nt = 0; nt < 8; nt++)
                    MMA_BF16(acc[mt][nt], aF[mt], bF[nt]);
        }
        __syncthreads();
    }

    // ---- epilogue
    const int r_in = lane >> 2;            // 0..7
    const int c_in = (lane & 3) * 2;       // 0,2,4,6

    if (mode == 0) {
        // stage (col-major, padded) then coalesced transposed writes
#pragma unroll
        for (int mt = 0; mt < 2; mt++)
#pragma unroll
            for (int nt = 0; nt < 8; nt++) {
                int colL = wn * 64 + nt * 8 + c_in;
#pragma unroll
                for (int half = 0; half < 2; half++) {
                    int rowL = wm * 32 + mt * 16 + r_in + half * 8;
                    float v0 = acc[mt][nt][half * 2 + 0] + bias[n0 + colL];
                    float v1 = acc[mt][nt][half * 2 + 1] + bias[n0 + colL + 1];
                    sm.tr[colL * TRS + rowL]       = __float2bfloat16(v0);
                    sm.tr[(colL + 1) * TRS + rowL] = __float2bfloat16(v1);
                }
            }
        __syncthreads();
        int col = tid >> 1, seg = tid & 1;
        int cg = n0 + col;
        int h = cg / Ee, e = cg - h * Ee;
        int b = m0 >> 10, mbase = (m0 & 1023) + seg * 64;
        __nv_bfloat16* dst = Cvt + ((long)(b * Ee + e)) * KV + h * 1024 + mbase;
        const __nv_bfloat16* srcp = &sm.tr[col * TRS + seg * 64];
#pragma unroll
        for (int i = 0; i < 8; i++)
            *(float4*)(dst + i * 8) = *(const float4*)(srcp + i * 8);
        return;
    }

#pragma unroll
    for (int mt = 0; mt < 2; mt++) {
#pragma unroll
        for (int nt = 0; nt < 8; nt++) {
            int col0 = n0 + wn * 64 + nt * 8 + c_in;
#pragma unroll
            for (int half = 0; half < 2; half++) {
                int row = m0 + wm * 32 + mt * 16 + r_in + half * 8;
                float v0 = acc[mt][nt][half * 2 + 0];
                float v1 = acc[mt][nt][half * 2 + 1];
                if (mode == 1) {
                    if (bias) { v0 += bias[col0]; v1 += bias[col0 + 1]; }
                    const float* rs = res + (long)bz * sRes + (long)row * ldc + col0;
                    float2 rv = *(const float2*)rs;
                    *(float2*)(Cf + (long)bz * sC + (long)row * ldc + col0) = make_float2(v0 + rv.x, v1 + rv.y);
                } else if (mode == 3) {
                    int b = bz / Hh, h = bz - b * Hh;
                    long addr = ((long)b * 1024 + row) * KV + h * 1024 + col0;
                    *(float2*)(Cf + addr) = make_float2(v0, v1);
                } else if (mode == 2) {
                    int b = row >> 10, n = row & 1023;
                    v0 += bias[col0]; v1 += bias[col0 + 1];
                    int h = col0 >> 6, d = col0 & 63;
                    long addr = (((long)(b * Hh + h) * 1024 + n) << 6) + d;
                    *(__nv_bfloat162*)(Cvt + addr) = __nv_bfloat162(__float2bfloat16(v0), __float2bfloat16(v1));
                } else { // mode 4
                    v0 = fmaxf(v0 + bias[col0], 0.f);
                    v1 = fmaxf(v1 + bias[col0 + 1], 0.f);
                    __nv_bfloat16 h0 = __float2bfloat16(v0), h1b = __float2bfloat16(v1);
                    __nv_bfloat16 l0 = __float2bfloat16(v0 - __bfloat162float(h0));
                    __nv_bfloat16 l1 = __float2bfloat16(v1 - __bfloat162float(h1b));
                    __nv_bfloat16* dst = Cvt + (long)row * KE3;
                    __nv_bfloat162 hp = __nv_bfloat162(h0, h1b);
                    *(__nv_bfloat162*)(dst + col0) = hp;
                    *(__nv_bfloat162*)(dst + 768 + col0) = hp;
                    *(__nv_bfloat162*)(dst + 1536 + col0) = __nv_bfloat162(l0, l1);
                }
            }
        }
    }
}

// ================= launch =================
extern "C" void kernel_launch(void* const* d_in, const int* in_sizes, int n_in,
                              void* d_out, int out_size) {
    const float* x     = (const float*)d_in[0];
    const float* y     = (const float*)d_in[1];
    const float* ln1_g = (const float*)d_in[2];
    const float* ln1_b = (const float*)d_in[3];
    const float* ln2_g = (const float*)d_in[4];
    const float* ln2_b = (const float*)d_in[5];
    const float* ln3_g = (const float*)d_in[6];
    const float* ln3_b = (const float*)d_in[7];
    const float* wq    = (const float*)d_in[8];
    const float* bq    = (const float*)d_in[9];
    const float* wk    = (const float*)d_in[10];
    const float* bk    = (const float*)d_in[11];
    const float* wv    = (const float*)d_in[12];
    const float* bv    = (const float*)d_in[13];
    const float* w_in  = (const float*)d_in[14];
    const float* b_in  = (const float*)d_in[15];
    const float* w_out = (const float*)d_in[16];
    const float* b_out = (const float*)d_in[17];

    float* out1 = (float*)d_out;
    float* yn   = out1 + (long)Bb * Nn * Ee;

    float *xn, *sb, *hb, *hnb;
    __nv_bfloat16 *sa, *vtb, *xa, *ya, *wvt, *wqt, *wkt, *wia, *woa, *qbh, *kbh, *hna, *ta;
    cudaGetSymbolAddress((void**)&xn,  g_xn);
    cudaGetSymbolAddress((void**)&sb,  g_s);
    cudaGetSymbolAddress((void**)&hb,  g_h);
    cudaGetSymbolAddress((void**)&hnb, g_hn);
    cudaGetSymbolAddress((void**)&sa,  g_sa);
    cudaGetSymbolAddress((void**)&vtb, g_vtb);
    cudaGetSymbolAddress((void**)&xa,  g_xa);
    cudaGetSymbolAddress((void**)&ya,  g_ya);
    cudaGetSymbolAddress((void**)&wvt, g_wvt);
    cudaGetSymbolAddress((void**)&wqt, g_wqt);
    cudaGetSymbolAddress((void**)&wkt, g_wkt);
    cudaGetSymbolAddress((void**)&wia, g_wia);
    cudaGetSymbolAddress((void**)&woa, g_woa);
    cudaGetSymbolAddress((void**)&qbh, g_qbh);
    cudaGetSymbolAddress((void**)&kbh, g_kbh);
    cudaGetSymbolAddress((void**)&hna, g_hna);
    cudaGetSymbolAddress((void**)&ta,  g_ta);

    // 1) LayerNorms (fp32 + bf16 copies)
    ln_bf16_kernel<<<Bb * Nn, 256>>>(x, xn, xa, ln1_g, ln1_b);
    ln_bf16_kernel<<<Bb * Mm, 256>>>(y, yn, ya, ln2_g, ln2_b);

    // 2) weight conversions
    {
        dim3 blk(32, 32);
        conv_wt_kernel<<<dim3(24, 288), blk>>>(wv, wvt, Ee * Hh);
        conv_wt_kernel<<<dim3(24, 24), blk>>>(wq, wqt, Ll);
        conv_wt_kernel<<<dim3(24, 24), blk>>>(wk, wkt, Ll);
        conv_wt_aug_kernel<<<dim3(24, 24), blk>>>(w_in, wia);
        conv_wt_aug_kernel<<<dim3(24, 24), blk>>>(w_out, woa);
    }

    // 3) q, k projections (bf16 mma) -> [b][h][n][64]
    {
        dim3 g(Ll / 128, (Bb * Nn) / 128);
        gemm_mma_kernel<<<g, 256>>>(xa, wqt, Ee, 0, 0, bq, nullptr, 0, nullptr, 0, 0, qbh, 2);
        gemm_mma_kernel<<<g, 256>>>(ya, wkt, Ee, 0, 0, bk, nullptr, 0, nullptr, 0, 0, kbh, 2);
    }

    // 4) v projection (bf16 mma) -> vtB [(b,e)][h*1024+m], coalesced epilogue
    {
        dim3 g((Ee * Hh) / 128, (Bb * Mm) / 128);
        gemm_mma_kernel<<<g, 256>>>(ya, wvt, Ee, 0, 0, bv, nullptr, 0, nullptr, 0, 0, vtb, 0);
    }

    // 5) scores (bf16 mma, K=64)
    {
        dim3 g(Mm / 128, Nn / 128, Bb * Hh);
        gemm_mma_kernel<<<g, 256>>>(qbh, kbh, HDd, (long)Nn * HDd, (long)Mm * HDd,
                                    nullptr, nullptr, 0, sb, 0, 0, nullptr, 3);
    }

    // 6) softmax -> bf16 probs
    softmax_bf16_kernel<<<Bb * Nn * Hh, 256>>>(sb, sa);

    // 7) dx (bf16 mma): h = s @ vt + xn
    {
        dim3 g(Ee / 128, Nn / 128, Bb);
        gemm_mma_kernel<<<g, 256>>>(sa, vtb, KV,
                                    (long)Nn * KV, (long)Ee * KV, nullptr,
                                    xn, (long)Nn * Ee, hb, (long)Nn * Ee, Ee,
                                    nullptr, 1);
    }

    // 8) LN3 (fp32 + aug bf16 rows)
    ln_aug_kernel<<<Bb * Nn, 256>>>(hb, hnb, hna, ln3_g, ln3_b);

    // 9) MLP (x3-augmented bf16 mma)
    {
        dim3 g(Ll / 128, (Bb * Nn) / 128);
        gemm_mma_kernel<<<g, 256>>>(hna, wia, KE3, 0, 0, b_in, nullptr, 0, nullptr, 0, 0, ta, 4);
        gemm_mma_kernel<<<g, 256>>>(ta, woa, KE3, 0, 0, b_out, hnb, 0, out1, 0, Ee, nullptr, 1);
    }
}

// round 10
// speedup vs baseline: 4.4127x; 1.0301x over previous
#include <cuda_runtime.h>
#include <cuda_bf16.h>
#include <cstdint>

// Problem constants
#define Ee 768
#define Ll 768
#define Hh 12
#define HDd 64
#define Bb 8
#define Nn 1024
#define Mm 1024
#define KV 12288           // H*M : K of the dx GEMM
#define KE3 2304           // 3*E augmented K for MLP

// ---------------- scratch (device globals) ----------------
__device__ float g_xn[Bb * Nn * Ee];
__device__ __nv_bfloat16 g_sa [(long)Bb * Nn * KV];              // bf16 probs [(b,n)][h*1024+m]
__device__ __nv_bfloat16 g_vtb[(long)Bb * Ee * KV];              // bf16 v [(b,e)][h*1024+m]
__device__ __nv_bfloat16 g_xa [Bb * Nn * Ee];                    // bf16 xn
__device__ __nv_bfloat16 g_ya [Bb * Mm * Ee];                    // bf16 yn
__device__ __nv_bfloat16 g_wvt[(long)(Ee * Hh) * Ee];            // bf16 wv^T [9216][768]
__device__ __nv_bfloat16 g_wqt[Ll * Ee];                         // bf16 wq^T
__device__ __nv_bfloat16 g_wkt[Ll * Ee];                         // bf16 wk^T
__device__ __nv_bfloat16 g_wia[Ll * KE3];                        // aug w_in^T [768][2304]
__device__ __nv_bfloat16 g_woa[Ee * KE3];                        // aug w_out^T [768][2304]
__device__ __nv_bfloat16 g_qbh[(long)Bb * Hh * Nn * HDd];        // q [b][h][n][64]
__device__ __nv_bfloat16 g_kbh[(long)Bb * Hh * Mm * HDd];        // k [b][h][m][64]
__device__ __nv_bfloat16 g_hna[(long)Bb * Nn * KE3];             // aug hn rows [Ah|Ah|Al]
__device__ __nv_bfloat16 g_ta [(long)Bb * Nn * KE3];             // aug relu(t) rows
__device__ float g_h [Bb * Nn * Ee];
__device__ float g_hn[Bb * Nn * Ee];

// ================= helpers =================
__device__ __forceinline__ uint32_t smem_u32(const void* p) {
    uint32_t a;
    asm("{ .reg .u64 t; cvta.to.shared.u64 t, %1; cvt.u32.u64 %0, t; }" : "=r"(a) : "l"(p));
    return a;
}

#define CP_ASYNC16(dst, src) \
    asm volatile("cp.async.cg.shared.global [%0], [%1], 16;" :: "r"(dst), "l"(src))
#define CP_COMMIT() asm volatile("cp.async.commit_group;" ::: "memory")
#define CP_WAIT1()  asm volatile("cp.async.wait_group 1;" ::: "memory")
#define CP_WAIT0()  asm volatile("cp.async.wait_group 0;" ::: "memory")

#define LDSM4(r0, r1, r2, r3, addr) \
    asm volatile("ldmatrix.sync.aligned.m8n8.x4.shared.b16 {%0,%1,%2,%3}, [%4];" \
        : "=r"(r0), "=r"(r1), "=r"(r2), "=r"(r3) : "r"(addr))

#define MMA_BF16(d, a, b) \
    asm volatile("mma.sync.aligned.m16n8k16.row.col.f32.bf16.bf16.f32 " \
        "{%0,%1,%2,%3}, {%4,%5,%6,%7}, {%8,%9}, {%0,%1,%2,%3};" \
        : "+f"((d)[0]), "+f"((d)[1]), "+f"((d)[2]), "+f"((d)[3]) \
        : "r"((a)[0]), "r"((a)[1]), "r"((a)[2]), "r"((a)[3]), "r"((b)[0]), "r"((b)[1]))

// ================= reductions =================
__device__ __forceinline__ float blockReduceSum(float val, float* sbuf) {
    int lane = threadIdx.x & 31, wid = threadIdx.x >> 5;
#pragma unroll
    for (int o = 16; o > 0; o >>= 1) val += __shfl_xor_sync(0xffffffffu, val, o);
    if (lane == 0) sbuf[wid] = val;
    __syncthreads();
    if (wid == 0) {
        float r = (lane < (int)(blockDim.x >> 5)) ? sbuf[lane] : 0.f;
#pragma unroll
        for (int o = 16; o > 0; o >>= 1) r += __shfl_xor_sync(0xffffffffu, r, o);
        if (lane == 0) sbuf[32] = r;
    }
    __syncthreads();
    return sbuf[32];
}

// ================= LayerNorm variants =================
__global__ void ln_bf16_kernel(const float* __restrict__ x, float* __restrict__ o,
                               __nv_bfloat16* __restrict__ ob,
                               const float* __restrict__ g, const float* __restrict__ bt) {
    __shared__ float sbuf[33];
    long row = blockIdx.x;
    const float* p = x + row * Ee;
    int t = threadIdx.x;
    float v0 = p[t], v1 = p[t + 256], v2 = p[t + 512];
    float sum = blockReduceSum(v0 + v1 + v2, sbuf);
    float mean = sum * (1.f / 768.f);
    float d0 = v0 - mean, d1 = v1 - mean, d2 = v2 - mean;
    __syncthreads();
    float sq = blockReduceSum(d0 * d0 + d1 * d1 + d2 * d2, sbuf);
    float rstd = rsqrtf(sq * (1.f / 768.f) + 1e-5f);
    float r0 = d0 * rstd * g[t]       + bt[t];
    float r1 = d1 * rstd * g[t + 256] + bt[t + 256];
    float r2 = d2 * rstd * g[t + 512] + bt[t + 512];
    float* q = o + row * Ee;
    q[t] = r0; q[t + 256] = r1; q[t + 512] = r2;
    __nv_bfloat16* qb2 = ob + row * Ee;
    qb2[t] = __float2bfloat16(r0);
    qb2[t + 256] = __float2bfloat16(r1);
    qb2[t + 512] = __float2bfloat16(r2);
}

__global__ void ln_aug_kernel(const float* __restrict__ x, float* __restrict__ o,
                              __nv_bfloat16* __restrict__ oa,
                              const float* __restrict__ g, const float* __restrict__ bt) {
    __shared__ float sbuf[33];
    long row = blockIdx.x;
    const float* p = x + row * Ee;
    int t = threadIdx.x;
    float v0 = p[t], v1 = p[t + 256], v2 = p[t + 512];
    float sum = blockReduceSum(v0 + v1 + v2, sbuf);
    float mean = sum * (1.f / 768.f);
    float d0 = v0 - mean, d1 = v1 - mean, d2 = v2 - mean;
    __syncthreads();
    float sq = blockReduceSum(d0 * d0 + d1 * d1 + d2 * d2, sbuf);
    float rstd = rsqrtf(sq * (1.f / 768.f) + 1e-5f);
    float r[3];
    r[0] = d0 * rstd * g[t]       + bt[t];
    r[1] = d1 * rstd * g[t + 256] + bt[t + 256];
    r[2] = d2 * rstd * g[t + 512] + bt[t + 512];
    float* q = o + row * Ee;
    q[t] = r[0]; q[t + 256] = r[1]; q[t + 512] = r[2];
    __nv_bfloat16* qa = oa + row * KE3;
#pragma unroll
    for (int i = 0; i < 3; i++) {
        int pos = t + i * 256;
        __nv_bfloat16 hi = __float2bfloat16(r[i]);
        __nv_bfloat16 lo = __float2bfloat16(r[i] - __bfloat162float(hi));
        qa[pos] = hi; qa[768 + pos] = hi; qa[1536 + pos] = lo;
    }
}

// ========== weight transpose convs ==========
__global__ void conv_wt_kernel(const float* __restrict__ w, __nv_bfloat16* __restrict__ wt, int ncols) {
    __shared__ float tile[32][33];
    int k0 = blockIdx.x * 32, n0 = blockIdx.y * 32;
    int tx = threadIdx.x, ty = threadIdx.y;
    tile[ty][tx] = w[(long)(k0 + ty) * ncols + n0 + tx];
    __syncthreads();
    int n = n0 + ty, k = k0 + tx;
    wt[(long)n * Ee + k] = __float2bfloat16(tile[tx][ty]);
}

__global__ void conv_wt_aug_kernel(const float* __restrict__ w, __nv_bfloat16* __restrict__ wt) {
    __shared__ float tile[32][33];
    int k0 = blockIdx.x * 32, n0 = blockIdx.y * 32;
    int tx = threadIdx.x, ty = threadIdx.y;
    tile[ty][tx] = w[(long)(k0 + ty) * Ee + n0 + tx];
    __syncthreads();
    int n = n0 + ty, k = k0 + tx;
    float v = tile[tx][ty];
    __nv_bfloat16 hi = __float2bfloat16(v);
    __nv_bfloat16 lo = __float2bfloat16(v - __bfloat162float(hi));
    __nv_bfloat16* dst = wt + (long)n * KE3;
    dst[k] = hi; dst[768 + k] = lo; dst[1536 + k] = hi;
}

// ================= fused attention probs kernel =================
// grid (Nn/128, Bb*Hh). Loads Q tile (128x64) + full K (1024x64) into smem,
// pass 1: scores via mma -> per-row running (max, sum); pass 2: recompute,
// write normalized bf16 probs directly to sa[(b,n)*KV + h*1024 + m].
// smem layout (dynamic): Q [2ch][128][32] 16KB | K [8mt][2ch][128][32] 128KB | red 2KB
__global__ void __launch_bounds__(256) attn_probs_kernel(
    const __nv_bfloat16* __restrict__ qbh, const __nv_bfloat16* __restrict__ kbh,
    __nv_bfloat16* __restrict__ sa)
{
    extern __shared__ char dsm[];
    const uint32_t Qs = smem_u32(dsm);
    const uint32_t Ks = Qs + 16384;
    float* mred = (float*)(dsm + 16384 + 131072);   // [2][128]
    float* sred = mred + 256;                        // [2][128]

    const int tid = threadIdx.x, wid = tid >> 5, lane = tid & 31;
    const int n0 = blockIdx.x * 128;
    const int bh = blockIdx.y;
    const int b = bh / Hh, h = bh - b * Hh;

    const __nv_bfloat16* qsrc = qbh + ((long)bh * 1024 + n0) * HDd;
    const __nv_bfloat16* ksrc = kbh + (long)bh * 1024 * HDd;

    // ---- load Q (1024 16B-units) and K (8192 units) via cp.async
#pragma unroll
    for (int i = 0; i < 4; i++) {
        int u = tid + 256 * i;
        int row = u >> 3, s = u & 7;
        int ch = s >> 2, sg = s & 3;
        uint32_t dst = Qs + ch * 8192 + row * 64 + (uint32_t)((sg ^ ((row >> 1) & 3)) << 4);
        CP_ASYNC16(dst, qsrc + row * HDd + s * 8);
    }
#pragma unroll
    for (int i = 0; i < 32; i++) {
        int u = tid + 256 * i;
        int row = u >> 3, s = u & 7;
        int mt = row >> 7, rowL = row & 127;
        int ch = s >> 2, sg = s & 3;
        uint32_t dst = Ks + mt * 16384 + ch * 8192 + rowL * 64 + (uint32_t)((sg ^ ((rowL >> 1) & 3)) << 4);
        CP_ASYNC16(dst, ksrc + row * HDd + s * 8);
    }
    CP_COMMIT();
    CP_WAIT0();
    __syncthreads();

    // ---- warp indexing (same as gemm kernel)
    const int wm = wid & 3, wn = wid >> 2;
    const int lrow = lane & 7;
    int rowA[2], rowB[4];
#pragma unroll
    for (int mt = 0; mt < 2; mt++) rowA[mt] = wm * 32 + mt * 16 + ((lane >> 3) & 1) * 8 + lrow;
#pragma unroll
    for (int np = 0; np < 4; np++) rowB[np] = wn * 64 + np * 16 + (lane >> 4) * 8 + lrow;
    const int segAq = (lane >> 4);
    const int segBq = ((lane >> 3) & 1);
    const int r_in = lane >> 2;
    const int c_in = (lane & 3) * 2;

    float rmax[4] = {-1e30f, -1e30f, -1e30f, -1e30f};
    float rsum[4] = {0.f, 0.f, 0.f, 0.f};
    const float sc = 0.125f;

    // ================= pass 1: running max/sum =================
    for (int mt8 = 0; mt8 < 8; mt8++) {
        float acc[2][8][4] = {};
        const uint32_t bTile = Ks + mt8 * 16384;
#pragma unroll
        for (int ch = 0; ch < 2; ch++) {
#pragma unroll
            for (int ks = 0; ks < 2; ks++) {
                uint32_t aF[2][4], bF[8][2];
#pragma unroll
                for (int mt = 0; mt < 2; mt++) {
                    int row = rowA[mt], seg = ks * 2 + segAq;
                    uint32_t ad = Qs + ch * 8192 + row * 64 + (uint32_t)((seg ^ ((row >> 1) & 3)) << 4);
                    LDSM4(aF[mt][0], aF[mt][1], aF[mt][2], aF[mt][3], ad);
                }
#pragma unroll
                for (int np = 0; np < 4; np++) {
                    int row = rowB[np], seg = ks * 2 + segBq;
                    uint32_t bd = bTile + ch * 8192 + row * 64 + (uint32_t)((seg ^ ((row >> 1) & 3)) << 4);
                    LDSM4(bF[2 * np][0], bF[2 * np][1], bF[2 * np + 1][0], bF[2 * np + 1][1], bd);
                }
#pragma unroll
                for (int mt = 0; mt < 2; mt++)
#pragma unroll
                    for (int nt = 0; nt < 8; nt++)
                        MMA_BF16(acc[mt][nt], aF[mt], bF[nt]);
            }
        }
        // per-row reduction (4 rows per thread: r = mt*2 + half)
#pragma unroll
        for (int mt = 0; mt < 2; mt++)
#pragma unroll
            for (int half = 0; half < 2; half++) {
                int r = mt * 2 + half;
                float tmax = -1e30f;
#pragma unroll
                for (int nt = 0; nt < 8; nt++) {
                    tmax = fmaxf(tmax, fmaxf(acc[mt][nt][half * 2], acc[mt][nt][half * 2 + 1]));
                }
                tmax *= sc;
                tmax = fmaxf(tmax, __shfl_xor_sync(0xffffffffu, tmax, 1));
                tmax = fmaxf(tmax, __shfl_xor_sync(0xffffffffu, tmax, 2));
                float tsum = 0.f;
#pragma unroll
                for (int nt = 0; nt < 8; nt++) {
                    tsum += __expf(acc[mt][nt][half * 2] * sc - tmax);
                    tsum += __expf(acc[mt][nt][half * 2 + 1] * sc - tmax);
                }
                tsum += __shfl_xor_sync(0xffffffffu, tsum, 1);
                tsum += __shfl_xor_sync(0xffffffffu, tsum, 2);
                float nm = fmaxf(rmax[r], tmax);
                rsum[r] = rsum[r] * __expf(rmax[r] - nm) + tsum * __expf(tmax - nm);
                rmax[r] = nm;
            }
    }

    // merge across the two wn warps sharing rows
    if ((lane & 3) == 0) {
#pragma unroll
        for (int mt = 0; mt < 2; mt++)
#pragma unroll
            for (int half = 0; half < 2; half++) {
                int r = mt * 2 + half;
                int row = wm * 32 + mt * 16 + r_in + half * 8;
                mred[wn * 128 + row] = rmax[r];
                sred[wn * 128 + row] = rsum[r];
            }
    }
    __syncthreads();
    float Mrow[4], Inv[4];
#pragma unroll
    for (int mt = 0; mt < 2; mt++)
#pragma unroll
        for (int half = 0; half < 2; half++) {
            int r = mt * 2 + half;
            int row = wm * 32 + mt * 16 + r_in + half * 8;
            float m0 = mred[row], m1 = mred[128 + row];
            float s0 = sred[row], s1 = sred[128 + row];
            float M = fmaxf(m0, m1);
            float S = s0 * __expf(m0 - M) + s1 * __expf(m1 - M);
            Mrow[r] = M; Inv[r] = 1.f / S;
        }

    // ================= pass 2: recompute + write probs =================
    __nv_bfloat16* outb = sa + ((long)b * 1024 + n0) * KV + h * 1024;
    for (int mt8 = 0; mt8 < 8; mt8++) {
        float acc[2][8][4] = {};
        const uint32_t bTile = Ks + mt8 * 16384;
#pragma unroll
        for (int ch = 0; ch < 2; ch++) {
#pragma unroll
            for (int ks = 0; ks < 2; ks++) {
                uint32_t aF[2][4], bF[8][2];
#pragma unroll
                for (int mt = 0; mt < 2; mt++) {
                    int row = rowA[mt], seg = ks * 2 + segAq;
                    uint32_t ad = Qs + ch * 8192 + row * 64 + (uint32_t)((seg ^ ((row >> 1) & 3)) << 4);
                    LDSM4(aF[mt][0], aF[mt][1], aF[mt][2], aF[mt][3], ad);
                }
#pragma unroll
                for (int np = 0; np < 4; np++) {
                    int row = rowB[np], seg = ks * 2 + segBq;
                    uint32_t bd = bTile + ch * 8192 + row * 64 + (uint32_t)((seg ^ ((row >> 1) & 3)) << 4);
                    LDSM4(bF[2 * np][0], bF[2 * np][1], bF[2 * np + 1][0], bF[2 * np + 1][1], bd);
                }
#pragma unroll
                for (int mt = 0; mt < 2; mt++)
#pragma unroll
                    for (int nt = 0; nt < 8; nt++)
                        MMA_BF16(acc[mt][nt], aF[mt], bF[nt]);
            }
        }
#pragma unroll
        for (int mt = 0; mt < 2; mt++)
#pragma unroll
            for (int half = 0; half < 2; half++) {
                int r = mt * 2 + half;
                int row = wm * 32 + mt * 16 + r_in + half * 8;
#pragma unroll
                for (int nt = 0; nt < 8; nt++) {
                    int col = mt8 * 128 + wn * 64 + nt * 8 + c_in;
                    float p0 = __expf(acc[mt][nt][half * 2] * sc - Mrow[r]) * Inv[r];
                    float p1 = __expf(acc[mt][nt][half * 2 + 1] * sc - Mrow[r]) * Inv[r];
                    *(__nv_bfloat162*)(outb + (long)row * KV + col) =
                        __nv_bfloat162(__float2bfloat16(p0), __float2bfloat16(p1));
                }
            }
    }
}

// ================= bf16 tensor-core GEMM via mma.sync =================
// 3-stage cp.async pipeline, one __syncthreads per 32-K chunk.
// mode 0: v-proj: smem-transposed coalesced bf16 writes to Cvt[(b*E+e)*KV + h*1024+m]
// mode 1: fp32 out = acc (+bias) + res
// mode 2: q/k scatter: bf16(acc+bias) -> Cvt[((b*H+h)*1024+n)*64+d]
// mode 4: relu-aug rows -> Cvt[row*2304 + {col, 768+col}]=hi, [1536+col]=lo
#define TRS 136
__global__ void __launch_bounds__(256) gemm_mma_kernel(
    const __nv_bfloat16* __restrict__ A, const __nv_bfloat16* __restrict__ Bm,
    int Kp, long sAb, long sBb,
    const float* __restrict__ bias,
    const float* __restrict__ res, long sRes, float* __restrict__ Cf, long sC, int ldc,
    __nv_bfloat16* __restrict__ Cvt, int mode)
{
    __shared__ union {
        struct { __nv_bfloat16 A[3][128 * 32]; __nv_bfloat16 B[3][128 * 32]; } p;
        __nv_bfloat16 tr[128 * TRS];
    } sm;
    const int tid = threadIdx.x, wid = tid >> 5, lane = tid & 31;
    const int bz = blockIdx.z;
    const int n0 = blockIdx.x * 128, m0 = blockIdx.y * 128;
    const __nv_bfloat16* Ap = A + (long)bz * sAb;
    const __nv_bfloat16* Bp = Bm + (long)bz * sBb;

    const int isA = (tid < 128);
    const int srow = isA ? tid : tid - 128;
    const __nv_bfloat16* gsrc = isA ? (Ap + (long)(m0 + srow) * Kp)
                                    : (Bp + (long)(n0 + srow) * Kp);
    uint32_t stage0 = smem_u32(isA ? (const void*)&sm.p.A[0][0] : (const void*)&sm.p.B[0][0]) + srow * 64;
    uint32_t dsw[4];
#pragma unroll
    for (int s2 = 0; s2 < 4; s2++) dsw[s2] = (uint32_t)((s2 ^ ((srow >> 1) & 3)) << 4);

    const int nchunks = Kp >> 5;

#pragma unroll
    for (int pc = 0; pc < 2; pc++) {
        if (pc < nchunks) {
            uint32_t d = stage0 + (uint32_t)(pc * 8192);
            const __nv_bfloat16* p = gsrc + (long)pc * 32;
#pragma unroll
            for (int s2 = 0; s2 < 4; s2++) CP_ASYNC16(d + dsw[s2], p + s2 * 8);
            CP_COMMIT();
        }
    }

    const int wm = wid & 3, wn = wid >> 2;
    const int lrow = lane & 7;
    int rowA[2], rowB[4];
#pragma unroll
    for (int mt = 0; mt < 2; mt++) rowA[mt] = wm * 32 + mt * 16 + ((lane >> 3) & 1) * 8 + lrow;
#pragma unroll
    for (int np = 0; np < 4; np++) rowB[np] = wn * 64 + np * 16 + (lane >> 4) * 8 + lrow;
    const int segAq = (lane >> 4);
    const int segBq = ((lane >> 3) & 1);
    const uint32_t smA0 = smem_u32(&sm.p.A[0][0]);
    const uint32_t smB0 = smem_u32(&sm.p.B[0][0]);

    float acc[2][8][4] = {};

    for (int c = 0; c < nchunks; c++) {
        if (c + 1 < nchunks) { CP_WAIT1(); } else { CP_WAIT0(); }
        __syncthreads();
        if (c + 2 < nchunks) {
            const int st = (c + 2) % 3;
            uint32_t d = stage0 + (uint32_t)(st * 8192);
            const __nv_bfloat16* p = gsrc + (long)(c + 2) * 32;
#pragma unroll
            for (int s2 = 0; s2 < 4; s2++) CP_ASYNC16(d + dsw[s2], p + s2 * 8);
            CP_COMMIT();
        }
        const int buf = c % 3;
        const uint32_t aB = smA0 + (uint32_t)(buf * 8192);
        const uint32_t bB = smB0 + (uint32_t)(buf * 8192);
#pragma unroll
        for (int ks = 0; ks < 2; ks++) {
            uint32_t aF[2][4];
            uint32_t bF[8][2];
#pragma unroll
            for (int mt = 0; mt < 2; mt++) {
                int row = rowA[mt], seg = ks * 2 + segAq;
                uint32_t ad = aB + row * 64 + (uint32_t)((seg ^ ((row >> 1) & 3)) << 4);
                LDSM4(aF[mt][0], aF[mt][1], aF[mt][2], aF[mt][3], ad);
            }
#pragma unroll
            for (int np = 0; np < 4; np++) {
                int row = rowB[np], seg = ks * 2 + segBq;
                uint32_t bd = bB + row * 64 + (uint32_t)((seg ^ ((row >> 1) & 3)) << 4);
                LDSM4(bF[2 * np][0], bF[2 * np][1], bF[2 * np + 1][0], bF[2 * np + 1][1], bd);
            }
#pragma unroll
            for (int mt = 0; mt < 2; mt++)
#pragma unroll
                for (int nt = 0; nt < 8; nt++)
                    MMA_BF16(acc[mt][nt], aF[mt], bF[nt]);
        }
        __syncthreads();
    }

    const int r_in = lane >> 2;
    const int c_in = (lane & 3) * 2;

    if (mode == 0) {
#pragma unroll
        for (int mt = 0; mt < 2; mt++)
#pragma unroll
            for (int nt = 0; nt < 8; nt++) {
                int colL = wn * 64 + nt * 8 + c_in;
#pragma unroll
                for (int half = 0; half < 2; half++) {
                    int rowL = wm * 32 + mt * 16 + r_in + half * 8;
                    float v0 = acc[mt][nt][half * 2 + 0] + bias[n0 + colL];
                    float v1 = acc[mt][nt][half * 2 + 1] + bias[n0 + colL + 1];
                    sm.tr[colL * TRS + rowL]       = __float2bfloat16(v0);
                    sm.tr[(colL + 1) * TRS + rowL] = __float2bfloat16(v1);
                }
            }
        __syncthreads();
        int col = tid >> 1, seg = tid & 1;
        int cg = n0 + col;
        int h = cg / Ee, e = cg - h * Ee;
        int b = m0 >> 10, mbase = (m0 & 1023) + seg * 64;
        __nv_bfloat16* dst = Cvt + ((long)(b * Ee + e)) * KV + h * 1024 + mbase;
        const __nv_bfloat16* srcp = &sm.tr[col * TRS + seg * 64];
#pragma unroll
        for (int i = 0; i < 8; i++)
            *(float4*)(dst + i * 8) = *(const float4*)(srcp + i * 8);
        return;
    }

#pragma unroll
    for (int mt = 0; mt < 2; mt++) {
#pragma unroll
        for (int nt = 0; nt < 8; nt++) {
            int col0 = n0 + wn * 64 + nt * 8 + c_in;
#pragma unroll
            for (int half = 0; half < 2; half++) {
                int row = m0 + wm * 32 + mt * 16 + r_in + half * 8;
                float v0 = acc[mt][nt][half * 2 + 0];
                float v1 = acc[mt][nt][half * 2 + 1];
                if (mode == 1) {
                    if (bias) { v0 += bias[col0]; v1 += bias[col0 + 1]; }
                    const float* rs = res + (long)bz * sRes + (long)row * ldc + col0;
                    float2 rv = *(const float2*)rs;
                    *(float2*)(Cf + (long)bz * sC + (long)row * ldc + col0) = make_float2(v0 + rv.x, v1 + rv.y);
                } else if (mode == 2) {
                    int b = row >> 10, n = row & 1023;
                    v0 += bias[col0]; v1 += bias[col0 + 1];
                    int h = col0 >> 6, d = col0 & 63;
                    long addr = (((long)(b * Hh + h) * 1024 + n) << 6) + d;
                    *(__nv_bfloat162*)(Cvt + addr) = __nv_bfloat162(__float2bfloat16(v0), __float2bfloat16(v1));
                } else { // mode 4
                    v0 = fmaxf(v0 + bias[col0], 0.f);
                    v1 = fmaxf(v1 + bias[col0 + 1], 0.f);
                    __nv_bfloat16 h0 = __float2bfloat16(v0), h1b = __float2bfloat16(v1);
                    __nv_bfloat16 l0 = __float2bfloat16(v0 - __bfloat162float(h0));
                    __nv_bfloat16 l1 = __float2bfloat16(v1 - __bfloat162float(h1b));
                    __nv_bfloat16* dst = Cvt + (long)row * KE3;
                    __nv_bfloat162 hp = __nv_bfloat162(h0, h1b);
                    *(__nv_bfloat162*)(dst + col0) = hp;
                    *(__nv_bfloat162*)(dst + 768 + col0) = hp;
                    *(__nv_bfloat162*)(dst + 1536 + col0) = __nv_bfloat162(l0, l1);
                }
            }
        }
    }
}

// ================= launch =================
extern "C" void kernel_launch(void* const* d_in, const int* in_sizes, int n_in,
                              void* d_out, int out_size) {
    const float* x     = (const float*)d_in[0];
    const float* y     = (const float*)d_in[1];
    const float* ln1_g = (const float*)d_in[2];
    const float* ln1_b = (const float*)d_in[3];
    const float* ln2_g = (const float*)d_in[4];
    const float* ln2_b = (const float*)d_in[5];
    const float* ln3_g = (const float*)d_in[6];
    const float* ln3_b = (const float*)d_in[7];
    const float* wq    = (const float*)d_in[8];
    const float* bq    = (const float*)d_in[9];
    const float* wk    = (const float*)d_in[10];
    const float* bk    = (const float*)d_in[11];
    const float* wv    = (const float*)d_in[12];
    const float* bv    = (const float*)d_in[13];
    const float* w_in  = (const float*)d_in[14];
    const float* b_in  = (const float*)d_in[15];
    const float* w_out = (const float*)d_in[16];
    const float* b_out = (const float*)d_in[17];

    float* out1 = (float*)d_out;
    float* yn   = out1 + (long)Bb * Nn * Ee;

    float *xn, *hb, *hnb;
    __nv_bfloat16 *sa, *vtb, *xa, *ya, *wvt, *wqt, *wkt, *wia, *woa, *qbh, *kbh, *hna, *ta;
    cudaGetSymbolAddress((void**)&xn,  g_xn);
    cudaGetSymbolAddress((void**)&hb,  g_h);
    cudaGetSymbolAddress((void**)&hnb, g_hn);
    cudaGetSymbolAddress((void**)&sa,  g_sa);
    cudaGetSymbolAddress((void**)&vtb, g_vtb);
    cudaGetSymbolAddress((void**)&xa,  g_xa);
    cudaGetSymbolAddress((void**)&ya,  g_ya);
    cudaGetSymbolAddress((void**)&wvt, g_wvt);
    cudaGetSymbolAddress((void**)&wqt, g_wqt);
    cudaGetSymbolAddress((void**)&wkt, g_wkt);
    cudaGetSymbolAddress((void**)&wia, g_wia);
    cudaGetSymbolAddress((void**)&woa, g_woa);
    cudaGetSymbolAddress((void**)&qbh, g_qbh);
    cudaGetSymbolAddress((void**)&kbh, g_kbh);
    cudaGetSymbolAddress((void**)&hna, g_hna);
    cudaGetSymbolAddress((void**)&ta,  g_ta);

    static bool attr_done = false;
    if (!attr_done) {
        cudaFuncSetAttribute(attn_probs_kernel, cudaFuncAttributeMaxDynamicSharedMemorySize, 16384 + 131072 + 2048);
        attr_done = true;
    }

    // 1) LayerNorms (fp32 + bf16 copies)
    ln_bf16_kernel<<<Bb * Nn, 256>>>(x, xn, xa, ln1_g, ln1_b);
    ln_bf16_kernel<<<Bb * Mm, 256>>>(y, yn, ya, ln2_g, ln2_b);

    // 2) weight conversions
    {
        dim3 blk(32, 32);
        conv_wt_kernel<<<dim3(24, 288), blk>>>(wv, wvt, Ee * Hh);
        conv_wt_kernel<<<dim3(24, 24), blk>>>(wq, wqt, Ll);
        conv_wt_kernel<<<dim3(24, 24), blk>>>(wk, wkt, Ll);
        conv_wt_aug_kernel<<<dim3(24, 24), blk>>>(w_in, wia);
        conv_wt_aug_kernel<<<dim3(24, 24), blk>>>(w_out, woa);
    }

    // 3) q, k projections (bf16 mma) -> [b][h][n][64]
    {
        dim3 g(Ll / 128, (Bb * Nn) / 128);
        gemm_mma_kernel<<<g, 256>>>(xa, wqt, Ee, 0, 0, bq, nullptr, 0, nullptr, 0, 0, qbh, 2);
        gemm_mma_kernel<<<g, 256>>>(ya, wkt, Ee, 0, 0, bk, nullptr, 0, nullptr, 0, 0, kbh, 2);
    }

    // 4) v projection (bf16 mma) -> vtB [(b,e)][h*1024+m]
    {
        dim3 g((Ee * Hh) / 128, (Bb * Mm) / 128);
        gemm_mma_kernel<<<g, 256>>>(ya, wvt, Ee, 0, 0, bv, nullptr, 0, nullptr, 0, 0, vtb, 0);
    }

    // 5+6) fused scores + softmax -> bf16 probs
    {
        dim3 g(Nn / 128, Bb * Hh);
        attn_probs_kernel<<<g, 256, 16384 + 131072 + 2048>>>(qbh, kbh, sa);
    }

    // 7) dx (bf16 mma): h = s @ vt + xn
    {
        dim3 g(Ee / 128, Nn / 128, Bb);
        gemm_mma_kernel<<<g, 256>>>(sa, vtb, KV,
                                    (long)Nn * KV, (long)Ee * KV, nullptr,
                                    xn, (long)Nn * Ee, hb, (long)Nn * Ee, Ee,
                                    nullptr, 1);
    }

    // 8) LN3 (fp32 + aug bf16 rows)
    ln_aug_kernel<<<Bb * Nn, 256>>>(hb, hnb, hna, ln3_g, ln3_b);

    // 9) MLP (x3-augmented bf16 mma)
    {
        dim3 g(Ll / 128, (Bb * Nn) / 128);
        gemm_mma_kernel<<<g, 256>>>(hna, wia, KE3, 0, 0, b_in, nullptr, 0, nullptr, 0, 0, ta, 4);
        gemm_mma_kernel<<<g, 256>>>(ta, woa, KE3, 0, 0, b_out, hnb, 0, out1, 0, Ee, nullptr, 1);
    }
}